// round 2
// baseline (speedup 1.0000x reference)
#include <cuda_runtime.h>
#include <cuda_bf16.h>
#include <math.h>

// Problem constants
#define BATCH 16
#define DIM 512
#define MIDC 32
#define HH 32
#define WW 32
#define NPIX 1024           // 32*32
#define NTOK 16384          // 16*1024
#define FDIM 2048

// ---------------- scratch (static device memory; no allocs) ----------------
__device__ float g_x[BATCH * DIM * NPIX];          // x after pe residual
__device__ float g_h[BATCH * MIDC * NPIX];         // conv mid activation
__device__ float g_kw[BATCH * DIM * NPIX];         // kg out, later reused for y (NCHW)
__device__ float g_Hw[BATCH * 256 * 32];
__device__ float g_Ww[BATCH * 256 * 32];
__device__ __nv_bfloat16 g_ybf[NTOK * DIM];        // LN'd tokens (NHWC), bf16
__device__ __nv_bfloat16 g_mid[NTOK * FDIM];       // MLP hidden, bf16
__device__ __nv_bfloat16 g_w1bf[FDIM * DIM];
__device__ __nv_bfloat16 g_w2bf[DIM * FDIM];

// ---------------- weight conversion ----------------
__global__ void cvt_weights(const float* __restrict__ w1, const float* __restrict__ w2,
                            __nv_bfloat16* __restrict__ o1, __nv_bfloat16* __restrict__ o2)
{
    int i = blockIdx.x * blockDim.x + threadIdx.x;
    if (i < FDIM * DIM) {
        o1[i] = __float2bfloat16(w1[i]);
        o2[i] = __float2bfloat16(w2[i]);
    }
}

// ---------------- conv1: 512->32, 3x3 SAME, fused BN(affine w/ stats)+ReLU ---
// grid: (rc=8, b=16, ocz=2), block 128 threads (4 rows x 32 cols), 16 oc/thread
__global__ __launch_bounds__(128) void conv1_bn_relu(
    const float* __restrict__ x, const float* __restrict__ w,
    const float* __restrict__ bng, const float* __restrict__ bnb,
    const float* __restrict__ bnm, const float* __restrict__ bnv,
    float* __restrict__ out)
{
    __shared__ float xs[8][6][34];
    __shared__ float ws[8][9][16];   // [ic][k][oc]
    int rc = blockIdx.x, b = blockIdx.y, ocz = blockIdx.z;
    int r0 = rc * 4;
    int tid = threadIdx.x;
    int ry = tid >> 5, cx = tid & 31;
    float acc[16];
#pragma unroll
    for (int i = 0; i < 16; i++) acc[i] = 0.f;
    const float* xb = x + (size_t)b * DIM * NPIX;

    for (int icb = 0; icb < 64; icb++) {
        int ic0 = icb * 8;
        for (int idx = tid; idx < 8 * 6 * 34; idx += 128) {
            int ic = idx / 204; int rem = idx - ic * 204;
            int rr = rem / 34; int cc = rem - rr * 34;
            int gr = r0 + rr - 1, gc = cc - 1;
            float v = 0.f;
            if (gr >= 0 && gr < 32 && gc >= 0 && gc < 32)
                v = xb[(size_t)(ic0 + ic) * NPIX + gr * 32 + gc];
            xs[ic][rr][cc] = v;
        }
        for (int idx = tid; idx < 8 * 9 * 16; idx += 128) {
            int oc = idx & 15; int k = (idx >> 4) % 9; int ic = idx / 144;
            ws[ic][k][oc] = w[((size_t)(ocz * 16 + oc) * DIM + ic0 + ic) * 9 + k];
        }
        __syncthreads();
#pragma unroll
        for (int ic = 0; ic < 8; ic++) {
            float xv[9];
#pragma unroll
            for (int ky = 0; ky < 3; ky++)
#pragma unroll
                for (int kx = 0; kx < 3; kx++)
                    xv[ky * 3 + kx] = xs[ic][ry + ky][cx + kx];
#pragma unroll
            for (int k = 0; k < 9; k++) {
                const float4* wp = (const float4*)&ws[ic][k][0];
#pragma unroll
                for (int o4 = 0; o4 < 4; o4++) {
                    float4 wv = wp[o4];
                    acc[o4 * 4 + 0] += wv.x * xv[k];
                    acc[o4 * 4 + 1] += wv.y * xv[k];
                    acc[o4 * 4 + 2] += wv.z * xv[k];
                    acc[o4 * 4 + 3] += wv.w * xv[k];
                }
            }
        }
        __syncthreads();
    }
    float* ob = out + (size_t)b * MIDC * NPIX + (r0 + ry) * 32 + cx;
#pragma unroll
    for (int oc = 0; oc < 16; oc++) {
        int ocg = ocz * 16 + oc;
        float inv = rsqrtf(bnv[ocg] + 1e-5f);
        float v = bng[ocg] * (acc[oc] - bnm[ocg]) * inv + bnb[ocg];
        ob[(size_t)ocg * NPIX] = fmaxf(v, 0.f);
    }
}

// ---------------- conv2: 32->512, 3x3 SAME + bias (+ optional residual) -----
// grid: (ocg=16, rc=8, b=16), block 256 = 32 oc x 8 col-groups; 4 rows x 4 cols/thread
__global__ __launch_bounds__(256) void conv2_bias_res(
    const float* __restrict__ h, const float* __restrict__ w2,
    const float* __restrict__ b2, const float* __restrict__ res,
    float* __restrict__ out)
{
    __shared__ float hs[32][6][34];
    __shared__ float ws[8][9][32];   // [ic][k][oc]
    int ocg = blockIdx.x, rc = blockIdx.y, b = blockIdx.z;
    int r0 = rc * 4;
    int tid = threadIdx.x;
    int oc_l = tid >> 3;
    int cg = (tid & 7) * 4;
    const float* hb = h + (size_t)b * MIDC * NPIX;

    for (int idx = tid; idx < 32 * 6 * 34; idx += 256) {
        int ic = idx / 204; int rem = idx - ic * 204;
        int rr = rem / 34; int cc = rem - rr * 34;
        int gr = r0 + rr - 1, gc = cc - 1;
        float v = 0.f;
        if (gr >= 0 && gr < 32 && gc >= 0 && gc < 32)
            v = hb[(size_t)ic * NPIX + gr * 32 + gc];
        hs[ic][rr][cc] = v;
    }
    float acc[4][4];
#pragma unroll
    for (int r = 0; r < 4; r++)
#pragma unroll
        for (int c = 0; c < 4; c++) acc[r][c] = 0.f;

    for (int icb = 0; icb < 4; icb++) {
        __syncthreads();
        for (int idx = tid; idx < 8 * 9 * 32; idx += 256) {
            int oc = idx & 31; int k = (idx >> 5) % 9; int ic = idx / 288;
            ws[ic][k][oc] = w2[((size_t)(ocg * 32 + oc) * MIDC + icb * 8 + ic) * 9 + k];
        }
        __syncthreads();
#pragma unroll
        for (int ic = 0; ic < 8; ic++) {
            int icg = icb * 8 + ic;
            float xv[6][6];
#pragma unroll
            for (int rr = 0; rr < 6; rr++)
#pragma unroll
                for (int cc = 0; cc < 6; cc++)
                    xv[rr][cc] = hs[icg][rr][cg + cc];
#pragma unroll
            for (int ky = 0; ky < 3; ky++)
#pragma unroll
                for (int kx = 0; kx < 3; kx++) {
                    float wv = ws[ic][ky * 3 + kx][oc_l];
#pragma unroll
                    for (int r = 0; r < 4; r++)
#pragma unroll
                        for (int c = 0; c < 4; c++)
                            acc[r][c] += wv * xv[r + ky][c + kx];
                }
        }
    }
    int oc = ocg * 32 + oc_l;
    float bv = b2[oc];
    size_t base = ((size_t)b * DIM + oc) * NPIX + r0 * 32 + cg;
#pragma unroll
    for (int r = 0; r < 4; r++) {
        float4 o;
        o.x = acc[r][0] + bv; o.y = acc[r][1] + bv;
        o.z = acc[r][2] + bv; o.w = acc[r][3] + bv;
        if (res) {
            float4 rv = *(const float4*)&res[base + r * 32];
            o.x += rv.x; o.y += rv.y; o.z += rv.z; o.w += rv.w;
        }
        *(float4*)&out[base + r * 32] = o;
    }
}

// ---------------- mean reductions: Hw (over w), Ww (over h) -----------------
__global__ void reduce_hw(const float* __restrict__ kw,
                          float* __restrict__ Hw, float* __restrict__ Ww)
{
    int warp = (blockIdx.x * blockDim.x + threadIdx.x) >> 5;
    int lane = threadIdx.x & 31;
    if (warp >= BATCH * DIM) return;
    int b = warp >> 9, c = warp & 511;
    const float* p = kw + ((size_t)b * DIM + c) * NPIX;
    float s = 0.f;
    if (c < 256) {
#pragma unroll
        for (int w = 0; w < 32; w++) s += p[lane * 32 + w];
        Hw[((size_t)b * 256 + c) * 32 + lane] = s * (1.f / 32.f);
    } else {
#pragma unroll
        for (int hh = 0; hh < 32; hh++) s += p[hh * 32 + lane];
        Ww[((size_t)b * 256 + (c - 256)) * 32 + lane] = s * (1.f / 32.f);
    }
}

// ---------------- circular 32x32 matmuls + bias, writes y (NCHW) ------------
// block: 256 threads = 4 planes x 64 threads; thread = 4x4 px tile
__global__ __launch_bounds__(256) void circ_kernel(
    const float* __restrict__ x, const float* __restrict__ Hw,
    const float* __restrict__ Ww, const float* __restrict__ bias,
    float* __restrict__ y)
{
    __shared__ float xs[4][32][36];
    __shared__ float kv[4][32];
    int p0 = blockIdx.x * 4;
    int tid = threadIdx.x;
    int lp = tid >> 6;
    int lt = tid & 63;
    int plane = p0 + lp;
    int b = plane >> 9, c = plane & 511;
    const float* xp = x + (size_t)plane * NPIX;
    for (int idx = lt; idx < NPIX; idx += 64) {
        int r = idx >> 5, cc = idx & 31;
        xs[lp][r][cc] = xp[idx];
    }
    if (lt < 32)
        kv[lp][lt] = (c < 256) ? Hw[((size_t)b * 256 + c) * 32 + lt]
                               : Ww[((size_t)b * 256 + (c - 256)) * 32 + lt];
    __syncthreads();

    int t_r = (lt >> 3) * 4;
    int t_c = (lt & 7) * 4;
    float acc[4][4];
#pragma unroll
    for (int r = 0; r < 4; r++)
#pragma unroll
        for (int cc = 0; cc < 4; cc++) acc[r][cc] = 0.f;
    float bv = bias[c];

    if (c < 256) {
        // y[i][w] = sum_j kv[(j-i)&31] * xs[j][w]
        float kr[32];
#pragma unroll
        for (int u = 0; u < 32; u++) kr[u] = kv[lp][(u - t_r) & 31];
#pragma unroll
        for (int j = 0; j < 32; j++) {
            float4 xv = *(const float4*)&xs[lp][j][t_c];
#pragma unroll
            for (int ri = 0; ri < 4; ri++) {
                float kk = kr[(j - ri) & 31];
                acc[ri][0] += kk * xv.x;
                acc[ri][1] += kk * xv.y;
                acc[ri][2] += kk * xv.z;
                acc[ri][3] += kk * xv.w;
            }
        }
    } else {
        // y[h][i] = sum_j kv[(j-i)&31] * xs[h][j]
        float kr[32];
#pragma unroll
        for (int u = 0; u < 32; u++) kr[u] = kv[lp][(u - t_c) & 31];
#pragma unroll
        for (int j = 0; j < 32; j++) {
            float xv[4];
#pragma unroll
            for (int ri = 0; ri < 4; ri++) xv[ri] = xs[lp][t_r + ri][j];
#pragma unroll
            for (int ci = 0; ci < 4; ci++) {
                float kk = kr[(j - ci) & 31];
#pragma unroll
                for (int ri = 0; ri < 4; ri++) acc[ri][ci] += kk * xv[ri];
            }
        }
    }
    float* yp = y + (size_t)plane * NPIX;
#pragma unroll
    for (int ri = 0; ri < 4; ri++) {
        float4 o;
        o.x = acc[ri][0] + bv; o.y = acc[ri][1] + bv;
        o.z = acc[ri][2] + bv; o.w = acc[ri][3] + bv;
        *(float4*)&yp[(t_r + ri) * 32 + t_c] = o;
    }
}

// ---------------- LayerNorm over channels, output bf16 tokens (NHWC) --------
__global__ __launch_bounds__(128) void ln_kernel(
    const float* __restrict__ y, const float* __restrict__ lnw,
    const float* __restrict__ lnb, __nv_bfloat16* __restrict__ out)
{
    int t = blockIdx.x;
    int b = t >> 10, hw = t & 1023;
    const float* yp = y + (size_t)b * DIM * NPIX + hw;
    int tid = threadIdx.x;
    int wid = tid >> 5, lane = tid & 31;
    float v[4];
    float s = 0.f, s2 = 0.f;
#pragma unroll
    for (int k = 0; k < 4; k++) {
        int c = tid * 4 + k;
        v[k] = yp[(size_t)c * NPIX];
        s += v[k]; s2 += v[k] * v[k];
    }
#pragma unroll
    for (int o = 16; o; o >>= 1) {
        s += __shfl_xor_sync(0xffffffffu, s, o);
        s2 += __shfl_xor_sync(0xffffffffu, s2, o);
    }
    __shared__ float rs[4], rs2[4];
    __shared__ float mu_sh, rstd_sh;
    if (lane == 0) { rs[wid] = s; rs2[wid] = s2; }
    __syncthreads();
    if (tid == 0) {
        float S = rs[0] + rs[1] + rs[2] + rs[3];
        float S2 = rs2[0] + rs2[1] + rs2[2] + rs2[3];
        float mu = S * (1.f / 512.f);
        float var = S2 * (1.f / 512.f) - mu * mu;
        mu_sh = mu;
        rstd_sh = rsqrtf(var + 1e-6f);
    }
    __syncthreads();
    float mu = mu_sh, rstd = rstd_sh;
    __nv_bfloat16 ob[4];
#pragma unroll
    for (int k = 0; k < 4; k++) {
        int c = tid * 4 + k;
        float o = (v[k] - mu) * rstd * lnw[c] + lnb[c];
        ob[k] = __float2bfloat16(o);
    }
    *(uint2*)&out[(size_t)t * DIM + tid * 4] = *(uint2*)ob;
}

// ---------------- bf16 MMA GEMMs ----------------
__device__ __forceinline__ void mma16816(float* d, const unsigned* a, const unsigned* b) {
    asm volatile(
        "mma.sync.aligned.m16n8k16.row.col.f32.bf16.bf16.f32 "
        "{%0,%1,%2,%3}, {%4,%5,%6,%7}, {%8,%9}, {%0,%1,%2,%3};\n"
        : "+f"(d[0]), "+f"(d[1]), "+f"(d[2]), "+f"(d[3])
        : "r"(a[0]), "r"(a[1]), "r"(a[2]), "r"(a[3]), "r"(b[0]), "r"(b[1]));
}

__device__ __forceinline__ float gelu_exact(float x) {
    return 0.5f * x * (1.f + erff(x * 0.70710678118654752f));
}

#define BM 128
#define BN 128
#define BKG 32
#define SSTR 48   // smem row stride in bf16 elems (96B: 16B-aligned, modest conflicts)

// GEMM1: C[16384,2048] = gelu(A[16384,512] * W1[2048,512]^T + b)
__global__ __launch_bounds__(256) void gemm1_gelu(
    const __nv_bfloat16* __restrict__ A, const __nv_bfloat16* __restrict__ Bw,
    const float* __restrict__ bias, __nv_bfloat16* __restrict__ C)
{
    const int K = DIM;
    __shared__ __nv_bfloat16 As[BM][SSTR];
    __shared__ __nv_bfloat16 Bs[BN][SSTR];
    int m0 = blockIdx.y * BM, n0 = blockIdx.x * BN;
    int tid = threadIdx.x;
    int wid = tid >> 5, lane = tid & 31;
    int wm = (wid & 1) * 64, wn = (wid >> 1) * 32;
    int g = lane >> 2, tg = lane & 3;
    float acc[4][4][4];
#pragma unroll
    for (int i = 0; i < 4; i++)
#pragma unroll
        for (int j = 0; j < 4; j++)
#pragma unroll
            for (int k = 0; k < 4; k++) acc[i][j][k] = 0.f;

    int lr = tid >> 1, lc = (tid & 1) * 16;
    for (int k0 = 0; k0 < K; k0 += BKG) {
        const __nv_bfloat16* ap = &A[(size_t)(m0 + lr) * K + k0 + lc];
        const __nv_bfloat16* bp = &Bw[(size_t)(n0 + lr) * K + k0 + lc];
        uint4 a0 = *(const uint4*)ap;
        uint4 a1 = *(const uint4*)(ap + 8);
        uint4 b0 = *(const uint4*)bp;
        uint4 b1 = *(const uint4*)(bp + 8);
        *(uint4*)&As[lr][lc]     = a0;
        *(uint4*)&As[lr][lc + 8] = a1;
        *(uint4*)&Bs[lr][lc]     = b0;
        *(uint4*)&Bs[lr][lc + 8] = b1;
        __syncthreads();
#pragma unroll
        for (int ks = 0; ks < 2; ks++) {
            int kb = ks * 16;
            unsigned af[4][4], bf[4][2];
#pragma unroll
            for (int mi = 0; mi < 4; mi++) {
                int r = wm + mi * 16;
                af[mi][0] = *(const unsigned*)&As[r + g][kb + tg * 2];
                af[mi][1] = *(const unsigned*)&As[r + g + 8][kb + tg * 2];
                af[mi][2] = *(const unsigned*)&As[r + g][kb + tg * 2 + 8];
                af[mi][3] = *(const unsigned*)&As[r + g + 8][kb + tg * 2 + 8];
            }
#pragma unroll
            for (int ni = 0; ni < 4; ni++) {
                int r = wn + ni * 8;
                bf[ni][0] = *(const unsigned*)&Bs[r + g][kb + tg * 2];
                bf[ni][1] = *(const unsigned*)&Bs[r + g][kb + tg * 2 + 8];
            }
#pragma unroll
            for (int mi = 0; mi < 4; mi++)
#pragma unroll
                for (int ni = 0; ni < 4; ni++)
                    mma16816(acc[mi][ni], af[mi], bf[ni]);
        }
        __syncthreads();
    }
#pragma unroll
    for (int mi = 0; mi < 4; mi++)
#pragma unroll
        for (int ni = 0; ni < 4; ni++) {
            int col = n0 + wn + ni * 8 + tg * 2;
            float b0 = bias[col], b1 = bias[col + 1];
            int row0 = m0 + wm + mi * 16 + g;
#pragma unroll
            for (int rr = 0; rr < 2; rr++) {
                int r = row0 + rr * 8;
                float v0 = gelu_exact(acc[mi][ni][rr * 2 + 0] + b0);
                float v1 = gelu_exact(acc[mi][ni][rr * 2 + 1] + b1);
                __nv_bfloat162 p;
                p.x = __float2bfloat16(v0);
                p.y = __float2bfloat16(v1);
                *(__nv_bfloat162*)&C[(size_t)r * FDIM + col] = p;
            }
        }
}

// GEMM2: out = x_in + gamma * (A[16384,2048] * W2[512,2048]^T + b), NCHW write
__global__ __launch_bounds__(256) void gemm2_res(
    const __nv_bfloat16* __restrict__ A, const __nv_bfloat16* __restrict__ Bw,
    const float* __restrict__ bias2, const float* __restrict__ gamma,
    const float* __restrict__ xin, float* __restrict__ out)
{
    const int K = FDIM;
    __shared__ __nv_bfloat16 As[BM][SSTR];
    __shared__ __nv_bfloat16 Bs[BN][SSTR];
    int m0 = blockIdx.y * BM, n0 = blockIdx.x * BN;
    int tid = threadIdx.x;
    int wid = tid >> 5, lane = tid & 31;
    int wm = (wid & 1) * 64, wn = (wid >> 1) * 32;
    int g = lane >> 2, tg = lane & 3;
    float acc[4][4][4];
#pragma unroll
    for (int i = 0; i < 4; i++)
#pragma unroll
        for (int j = 0; j < 4; j++)
#pragma unroll
            for (int k = 0; k < 4; k++) acc[i][j][k] = 0.f;

    int lr = tid >> 1, lc = (tid & 1) * 16;
    for (int k0 = 0; k0 < K; k0 += BKG) {
        const __nv_bfloat16* ap = &A[(size_t)(m0 + lr) * K + k0 + lc];
        const __nv_bfloat16* bp = &Bw[(size_t)(n0 + lr) * K + k0 + lc];
        uint4 a0 = *(const uint4*)ap;
        uint4 a1 = *(const uint4*)(ap + 8);
        uint4 b0 = *(const uint4*)bp;
        uint4 b1 = *(const uint4*)(bp + 8);
        *(uint4*)&As[lr][lc]     = a0;
        *(uint4*)&As[lr][lc + 8] = a1;
        *(uint4*)&Bs[lr][lc]     = b0;
        *(uint4*)&Bs[lr][lc + 8] = b1;
        __syncthreads();
#pragma unroll
        for (int ks = 0; ks < 2; ks++) {
            int kb = ks * 16;
            unsigned af[4][4], bf[4][2];
#pragma unroll
            for (int mi = 0; mi < 4; mi++) {
                int r = wm + mi * 16;
                af[mi][0] = *(const unsigned*)&As[r + g][kb + tg * 2];
                af[mi][1] = *(const unsigned*)&As[r + g + 8][kb + tg * 2];
                af[mi][2] = *(const unsigned*)&As[r + g][kb + tg * 2 + 8];
                af[mi][3] = *(const unsigned*)&As[r + g + 8][kb + tg * 2 + 8];
            }
#pragma unroll
            for (int ni = 0; ni < 4; ni++) {
                int r = wn + ni * 8;
                bf[ni][0] = *(const unsigned*)&Bs[r + g][kb + tg * 2];
                bf[ni][1] = *(const unsigned*)&Bs[r + g][kb + tg * 2 + 8];
            }
#pragma unroll
            for (int mi = 0; mi < 4; mi++)
#pragma unroll
                for (int ni = 0; ni < 4; ni++)
                    mma16816(acc[mi][ni], af[mi], bf[ni]);
        }
        __syncthreads();
    }
#pragma unroll
    for (int mi = 0; mi < 4; mi++)
#pragma unroll
        for (int ni = 0; ni < 4; ni++) {
            int col = n0 + wn + ni * 8 + tg * 2;
            float gb0 = gamma[col], gb1 = gamma[col + 1];
            float bb0 = bias2[col], bb1 = bias2[col + 1];
            int row0 = m0 + wm + mi * 16 + g;
#pragma unroll
            for (int rr = 0; rr < 2; rr++) {
                int r = row0 + rr * 8;
                int bI = r >> 10, hw = r & 1023;
                size_t i0 = ((size_t)bI * DIM + col) * NPIX + hw;
                size_t i1 = i0 + NPIX;
                out[i0] = xin[i0] + gb0 * (acc[mi][ni][rr * 2 + 0] + bb0);
                out[i1] = xin[i1] + gb1 * (acc[mi][ni][rr * 2 + 1] + bb1);
            }
        }
}

// ---------------- host launcher ----------------
extern "C" void kernel_launch(void* const* d_in, const int* in_sizes, int n_in,
                              void* d_out, int out_size)
{
    const float* x      = (const float*)d_in[0];
    const float* pe_w1  = (const float*)d_in[1];
    const float* pe_bng = (const float*)d_in[2];
    const float* pe_bnb = (const float*)d_in[3];
    const float* pe_bnm = (const float*)d_in[4];
    const float* pe_bnv = (const float*)d_in[5];
    const float* pe_w2  = (const float*)d_in[6];
    const float* pe_b2  = (const float*)d_in[7];
    const float* kg_w1  = (const float*)d_in[8];
    const float* kg_bng = (const float*)d_in[9];
    const float* kg_bnb = (const float*)d_in[10];
    const float* kg_bnm = (const float*)d_in[11];
    const float* kg_bnv = (const float*)d_in[12];
    const float* kg_w2  = (const float*)d_in[13];
    const float* kg_b2  = (const float*)d_in[14];
    const float* bias   = (const float*)d_in[15];
    const float* ln_w   = (const float*)d_in[16];
    const float* ln_b   = (const float*)d_in[17];
    const float* pw1_w  = (const float*)d_in[18];
    const float* pw1_b  = (const float*)d_in[19];
    const float* pw2_w  = (const float*)d_in[20];
    const float* pw2_b  = (const float*)d_in[21];
    const float* gamma  = (const float*)d_in[22];
    float* outp = (float*)d_out;

    float *px, *ph, *pkw, *pHw, *pWw;
    __nv_bfloat16 *pybf, *pmid, *pw1bf, *pw2bf;
    cudaGetSymbolAddress((void**)&px,  g_x);
    cudaGetSymbolAddress((void**)&ph,  g_h);
    cudaGetSymbolAddress((void**)&pkw, g_kw);
    cudaGetSymbolAddress((void**)&pHw, g_Hw);
    cudaGetSymbolAddress((void**)&pWw, g_Ww);
    cudaGetSymbolAddress((void**)&pybf,  g_ybf);
    cudaGetSymbolAddress((void**)&pmid,  g_mid);
    cudaGetSymbolAddress((void**)&pw1bf, g_w1bf);
    cudaGetSymbolAddress((void**)&pw2bf, g_w2bf);

    // weight bf16 conversion (for MLP)
    cvt_weights<<<(FDIM * DIM + 255) / 256, 256>>>(pw1_w, pw2_w, pw1bf, pw2bf);

    // pe branch
    conv1_bn_relu<<<dim3(8, 16, 2), 128>>>(x, pe_w1, pe_bng, pe_bnb, pe_bnm, pe_bnv, ph);
    conv2_bias_res<<<dim3(16, 8, 16), 256>>>(ph, pe_w2, pe_b2, x, px);
    // kg branch
    conv1_bn_relu<<<dim3(8, 16, 2), 128>>>(px, kg_w1, kg_bng, kg_bnb, kg_bnm, kg_bnv, ph);
    conv2_bias_res<<<dim3(16, 8, 16), 256>>>(ph, kg_w2, kg_b2, nullptr, pkw);

    // mean reductions
    reduce_hw<<<(BATCH * DIM * 32) / 256, 256>>>(pkw, pHw, pWw);

    // circular mixing + bias (writes y over g_kw)
    circ_kernel<<<(BATCH * DIM) / 4, 256>>>(px, pHw, pWw, bias, pkw);

    // layernorm -> bf16 tokens
    ln_kernel<<<NTOK, 128>>>(pkw, ln_w, ln_b, pybf);

    // MLP
    gemm1_gelu<<<dim3(FDIM / BN, NTOK / BM), 256>>>(pybf, pw1bf, pw1_b, pmid);
    gemm2_res<<<dim3(DIM / BN, NTOK / BM), 256>>>(pmid, pw2bf, pw2_b, gamma, x, outp);
}

// round 3
// speedup vs baseline: 1.9061x; 1.9061x over previous
#include <cuda_runtime.h>
#include <cuda_bf16.h>
#include <math.h>

#define BATCH 16
#define DIM 512
#define MIDC 32
#define NPIX 1024
#define NTOK 16384
#define FDIM 2048

typedef __nv_bfloat16 bf16;

// ---------------- scratch (static device memory) ----------------
__device__ bf16 g_xtok [NTOK * DIM];     // x tokens (NHWC)
__device__ bf16 g_xtok2[NTOK * DIM];     // x after pe residual (tokens)
__device__ bf16 g_htok [NTOK * MIDC];    // conv mid activation tokens
__device__ bf16 g_kwtok[NTOK * DIM];     // kg output tokens
__device__ float g_xp[BATCH * DIM * NPIX];  // x planes (NCHW) for circ
__device__ float g_y [BATCH * DIM * NPIX];  // circ output y (NCHW)
__device__ float g_Hw[BATCH * 256 * 32];
__device__ float g_Ww[BATCH * 256 * 32];
__device__ bf16 g_ybf[NTOK * DIM];       // LN'd tokens
__device__ bf16 g_mid[NTOK * FDIM];      // MLP hidden
__device__ bf16 g_w1bf[FDIM * DIM];
__device__ bf16 g_w2bf[DIM * FDIM];
__device__ bf16 g_w1pe[9 * MIDC * DIM];  // [off][oc][ic]
__device__ bf16 g_w1kg[9 * MIDC * DIM];
__device__ bf16 g_w2pe[9 * DIM * MIDC];  // [off][oc][ic]
__device__ bf16 g_w2kg[9 * DIM * MIDC];

// ---------------- weight conversions ----------------
__global__ void cvt_weights(const float* __restrict__ w1, const float* __restrict__ w2,
                            bf16* __restrict__ o1, bf16* __restrict__ o2)
{
    int i = blockIdx.x * blockDim.x + threadIdx.x;
    if (i < FDIM * DIM) {
        o1[i] = __float2bfloat16(w1[i]);
        o2[i] = __float2bfloat16(w2[i]);
    }
}

__global__ void cvt_convw(const float* __restrict__ pw1, const float* __restrict__ kw1,
                          const float* __restrict__ pw2, const float* __restrict__ kw2,
                          bf16* __restrict__ o1p, bf16* __restrict__ o1k,
                          bf16* __restrict__ o2p, bf16* __restrict__ o2k)
{
    int i = blockIdx.x * blockDim.x + threadIdx.x;
    if (i >= MIDC * DIM * 9) return;
    int off = i % 9;
    // w1: i = (oc*DIM + ic)*9 + off, oc<32, ic<512
    int ic = (i / 9) % DIM, oc = i / (9 * DIM);
    o1p[(off * MIDC + oc) * DIM + ic] = __float2bfloat16(pw1[i]);
    o1k[(off * MIDC + oc) * DIM + ic] = __float2bfloat16(kw1[i]);
    // w2: i = (oc2*MIDC + ic2)*9 + off, oc2<512, ic2<32
    int ic2 = (i / 9) % MIDC, oc2 = i / (9 * MIDC);
    o2p[(off * DIM + oc2) * MIDC + ic2] = __float2bfloat16(pw2[i]);
    o2k[(off * DIM + oc2) * MIDC + ic2] = __float2bfloat16(kw2[i]);
}

// ---------------- NCHW fp32 -> token bf16 transpose ----------------
// grid (8, 4, 16), block 256. tile: 128 hw x 128 c
__global__ __launch_bounds__(256) void nchw2tok(const float* __restrict__ X, bf16* __restrict__ T)
{
    __shared__ bf16 sm[128][136];
    int hw0 = blockIdx.x * 128, c0 = blockIdx.y * 128, b = blockIdx.z;
    int tid = threadIdx.x;
    const float* xp = X + ((size_t)b * DIM + c0) * NPIX + hw0;
#pragma unroll
    for (int i = 0; i < 16; i++) {
        int idx = tid + i * 256;
        int rc = idx >> 5, u = idx & 31;
        float4 v = *(const float4*)&xp[(size_t)rc * NPIX + u * 4];
        union { uint2 q; bf16 h[4]; } pk;
        pk.h[0] = __float2bfloat16(v.x); pk.h[1] = __float2bfloat16(v.y);
        pk.h[2] = __float2bfloat16(v.z); pk.h[3] = __float2bfloat16(v.w);
        *(uint2*)&sm[rc][u * 4] = pk.q;
    }
    __syncthreads();
    bf16* tp = T + ((size_t)(b * NPIX + hw0)) * DIM + c0;
#pragma unroll
    for (int i = 0; i < 8; i++) {
        int idx = tid + i * 256;
        int rt = idx >> 4, uu = idx & 15;
        union { uint4 q; bf16 h[8]; } pk;
#pragma unroll
        for (int j = 0; j < 8; j++) pk.h[j] = sm[uu * 8 + j][rt];
        *(uint4*)&tp[(size_t)rt * DIM + uu * 8] = pk.q;
    }
}

// ---------------- token bf16 -> NCHW fp32 transpose ----------------
__global__ __launch_bounds__(256) void tok2nchw(const bf16* __restrict__ T, float* __restrict__ X)
{
    __shared__ bf16 sm[128][136];
    int hw0 = blockIdx.x * 128, c0 = blockIdx.y * 128, b = blockIdx.z;
    int tid = threadIdx.x;
    const bf16* tp = T + ((size_t)(b * NPIX + hw0)) * DIM + c0;
#pragma unroll
    for (int i = 0; i < 8; i++) {
        int idx = tid + i * 256;
        int rt = idx >> 4, uu = idx & 15;
        *(uint4*)&sm[rt][uu * 8] = *(const uint4*)&tp[(size_t)rt * DIM + uu * 8];
    }
    __syncthreads();
    float* xp = X + ((size_t)b * DIM + c0) * NPIX + hw0;
#pragma unroll
    for (int i = 0; i < 16; i++) {
        int idx = tid + i * 256;
        int rc = idx >> 5, u = idx & 31;
        float4 v;
        v.x = __bfloat162float(sm[u * 4 + 0][rc]);
        v.y = __bfloat162float(sm[u * 4 + 1][rc]);
        v.z = __bfloat162float(sm[u * 4 + 2][rc]);
        v.w = __bfloat162float(sm[u * 4 + 3][rc]);
        *(float4*)&xp[(size_t)rc * NPIX + u * 4] = v;
    }
}

// ---------------- MMA helper ----------------
__device__ __forceinline__ void mma16816(float* d, const unsigned* a, const unsigned* b) {
    asm volatile(
        "mma.sync.aligned.m16n8k16.row.col.f32.bf16.bf16.f32 "
        "{%0,%1,%2,%3}, {%4,%5,%6,%7}, {%8,%9}, {%0,%1,%2,%3};\n"
        : "+f"(d[0]), "+f"(d[1]), "+f"(d[2]), "+f"(d[3])
        : "r"(a[0]), "r"(a[1]), "r"(a[2]), "r"(a[3]), "r"(b[0]), "r"(b[1]));
}

// ---------------- conv1 implicit GEMM: tokens(512) -> h tokens(32), BN+ReLU --
// M=16384 (BM=64/block), N=32, K = 9 offsets x 512. grid 256, block 256 (8 warps: 4m x 2n)
__global__ __launch_bounds__(256) void conv1_tok(
    const bf16* __restrict__ X, const bf16* __restrict__ W,
    const float* __restrict__ bng, const float* __restrict__ bnb,
    const float* __restrict__ bnm, const float* __restrict__ bnv,
    bf16* __restrict__ O)
{
    __shared__ bf16 As[64][72];
    __shared__ bf16 Bs[32][72];
    __shared__ bf16 Cs[64][48];
    __shared__ float sS[32], sT[32];
    int m0 = blockIdx.x * 64;
    int tid = threadIdx.x;
    if (tid < 32) {
        float inv = rsqrtf(bnv[tid] + 1e-5f);
        float s = bng[tid] * inv;
        sS[tid] = s;
        sT[tid] = bnb[tid] - bnm[tid] * s;
    }
    // A loader mapping: row ar (0..63), col block aq
    int ar = tid >> 2, aq = (tid & 3) * 16;
    int t = m0 + ar;
    int th = (t >> 5) & 31, tw = t & 31;
    // B loader mapping
    int br = tid >> 3, bq = (tid & 7) * 8;
    // warp layout
    int wid = tid >> 5, lane = tid & 31;
    int wm = (wid & 3) * 16, wn = (wid >> 2) * 16;
    int g = lane >> 2, tg = lane & 3;

    float acc[2][4];
#pragma unroll
    for (int i = 0; i < 2; i++)
#pragma unroll
        for (int j = 0; j < 4; j++) acc[i][j] = 0.f;

    for (int off = 0; off < 9; off++) {
        int dy = off / 3 - 1, dx = off % 3 - 1;
        bool valid = ((unsigned)(th + dy) < 32u) && ((unsigned)(tw + dx) < 32u);
        const bf16* srcA = X + ((long)(t + dy * 32 + dx)) * DIM;
        const bf16* srcB = W + (size_t)(off * MIDC + br) * DIM + bq;
        for (int k0 = 0; k0 < DIM; k0 += 64) {
            uint4 a0 = {0, 0, 0, 0}, a1 = {0, 0, 0, 0};
            if (valid) {
                a0 = *(const uint4*)&srcA[k0 + aq];
                a1 = *(const uint4*)&srcA[k0 + aq + 8];
            }
            *(uint4*)&As[ar][aq]     = a0;
            *(uint4*)&As[ar][aq + 8] = a1;
            *(uint4*)&Bs[br][bq] = *(const uint4*)&srcB[k0];
            __syncthreads();
#pragma unroll
            for (int kc = 0; kc < 4; kc++) {
                int kb = kc * 16;
                unsigned a[4], bfr[2][2];
                a[0] = *(const unsigned*)&As[wm + g][kb + tg * 2];
                a[1] = *(const unsigned*)&As[wm + g + 8][kb + tg * 2];
                a[2] = *(const unsigned*)&As[wm + g][kb + tg * 2 + 8];
                a[3] = *(const unsigned*)&As[wm + g + 8][kb + tg * 2 + 8];
#pragma unroll
                for (int ni = 0; ni < 2; ni++) {
                    bfr[ni][0] = *(const unsigned*)&Bs[wn + ni * 8 + g][kb + tg * 2];
                    bfr[ni][1] = *(const unsigned*)&Bs[wn + ni * 8 + g][kb + tg * 2 + 8];
                }
                mma16816(acc[0], a, bfr[0]);
                mma16816(acc[1], a, bfr[1]);
            }
            __syncthreads();
        }
    }
    // epilogue: BN + ReLU into Cs
#pragma unroll
    for (int ni = 0; ni < 2; ni++)
#pragma unroll
        for (int rr = 0; rr < 2; rr++)
#pragma unroll
            for (int j = 0; j < 2; j++) {
                int col = wn + ni * 8 + tg * 2 + j;
                int row = wm + g + rr * 8;
                float v = acc[ni][rr * 2 + j] * sS[col] + sT[col];
                Cs[row][col] = __float2bfloat16(fmaxf(v, 0.f));
            }
    __syncthreads();
    int orow = tid >> 2, oq = (tid & 3) * 8;
    *(uint4*)&O[(size_t)(m0 + orow) * MIDC + oq] = *(uint4*)&Cs[orow][oq];
}

// ---------------- conv2 implicit GEMM: h tokens(32) -> tokens(512) + bias (+res)
// M=16384 (BM=128), N=512 (BN=64), K = 9 x 32. grid (8, 128), block 256 (4m x 2n warps)
__global__ __launch_bounds__(256) void conv2_tok(
    const bf16* __restrict__ Hx, const bf16* __restrict__ W,
    const float* __restrict__ b2, const bf16* __restrict__ res,
    bf16* __restrict__ O)
{
    __shared__ bf16 As[128][40];
    __shared__ bf16 Bs[64][40];
    int n0 = blockIdx.x * 64, m0 = blockIdx.y * 128;
    int tid = threadIdx.x;
    int ar = tid >> 1, aq = (tid & 1) * 16;
    int t = m0 + ar;
    int th = (t >> 5) & 31, tw = t & 31;
    int br = tid >> 2, bq = (tid & 3) * 8;
    int wid = tid >> 5, lane = tid & 31;
    int wm = (wid & 3) * 32, wn = (wid >> 2) * 32;
    int g = lane >> 2, tg = lane & 3;

    float acc[2][4][4];
#pragma unroll
    for (int i = 0; i < 2; i++)
#pragma unroll
        for (int j = 0; j < 4; j++)
#pragma unroll
            for (int k = 0; k < 4; k++) acc[i][j][k] = 0.f;

    for (int off = 0; off < 9; off++) {
        int dy = off / 3 - 1, dx = off % 3 - 1;
        bool valid = ((unsigned)(th + dy) < 32u) && ((unsigned)(tw + dx) < 32u);
        uint4 a0 = {0, 0, 0, 0}, a1 = {0, 0, 0, 0};
        if (valid) {
            const bf16* srcA = Hx + ((long)(t + dy * 32 + dx)) * MIDC;
            a0 = *(const uint4*)&srcA[aq];
            a1 = *(const uint4*)&srcA[aq + 8];
        }
        *(uint4*)&As[ar][aq]     = a0;
        *(uint4*)&As[ar][aq + 8] = a1;
        *(uint4*)&Bs[br][bq] = *(const uint4*)&W[(size_t)(off * DIM + n0 + br) * MIDC + bq];
        __syncthreads();
#pragma unroll
        for (int kc = 0; kc < 2; kc++) {
            int kb = kc * 16;
            unsigned a[2][4], bfr[4][2];
#pragma unroll
            for (int mi = 0; mi < 2; mi++) {
                int r = wm + mi * 16;
                a[mi][0] = *(const unsigned*)&As[r + g][kb + tg * 2];
                a[mi][1] = *(const unsigned*)&As[r + g + 8][kb + tg * 2];
                a[mi][2] = *(const unsigned*)&As[r + g][kb + tg * 2 + 8];
                a[mi][3] = *(const unsigned*)&As[r + g + 8][kb + tg * 2 + 8];
            }
#pragma unroll
            for (int ni = 0; ni < 4; ni++) {
                bfr[ni][0] = *(const unsigned*)&Bs[wn + ni * 8 + g][kb + tg * 2];
                bfr[ni][1] = *(const unsigned*)&Bs[wn + ni * 8 + g][kb + tg * 2 + 8];
            }
#pragma unroll
            for (int mi = 0; mi < 2; mi++)
#pragma unroll
                for (int ni = 0; ni < 4; ni++)
                    mma16816(acc[mi][ni], a[mi], bfr[ni]);
        }
        __syncthreads();
    }
    // epilogue
    float bv0[4], bv1[4];
#pragma unroll
    for (int ni = 0; ni < 4; ni++) {
        int col = n0 + wn + ni * 8 + tg * 2;
        bv0[ni] = b2[col];
        bv1[ni] = b2[col + 1];
    }
#pragma unroll
    for (int mi = 0; mi < 2; mi++)
#pragma unroll
        for (int ni = 0; ni < 4; ni++)
#pragma unroll
            for (int rr = 0; rr < 2; rr++) {
                int row = m0 + wm + mi * 16 + g + rr * 8;
                size_t ad = (size_t)row * DIM + n0 + wn + ni * 8 + tg * 2;
                float v0 = acc[mi][ni][rr * 2 + 0] + bv0[ni];
                float v1 = acc[mi][ni][rr * 2 + 1] + bv1[ni];
                if (res) {
                    __nv_bfloat162 rv = *(const __nv_bfloat162*)&res[ad];
                    v0 += __bfloat162float(rv.x);
                    v1 += __bfloat162float(rv.y);
                }
                __nv_bfloat162 p;
                p.x = __float2bfloat16(v0);
                p.y = __float2bfloat16(v1);
                *(__nv_bfloat162*)&O[ad] = p;
            }
}

// ---------------- mean reductions from tokens ----------------
// Hw[b][c][h] = mean_w kwtok[(b*1024+h*32+w)*512 + c], c<256.  grid(32,16), 256 thr
__global__ void reduceH_tok(const bf16* __restrict__ T, float* __restrict__ Hw)
{
    int h = blockIdx.x, b = blockIdx.y, c = threadIdx.x;
    const bf16* p = T + (size_t)(b * NPIX + h * 32) * DIM + c;
    float s = 0.f;
#pragma unroll
    for (int w = 0; w < 32; w++) s += __bfloat162float(p[(size_t)w * DIM]);
    Hw[((size_t)b * 256 + c) * 32 + h] = s * (1.f / 32.f);
}
// Ww[b][c'][w] = mean_h kwtok[(b*1024+h*32+w)*512 + 256 + c'].  grid(32,16), 256 thr
__global__ void reduceW_tok(const bf16* __restrict__ T, float* __restrict__ Ww)
{
    int w = blockIdx.x, b = blockIdx.y, c = threadIdx.x;
    const bf16* p = T + (size_t)(b * NPIX + w) * DIM + 256 + c;
    float s = 0.f;
#pragma unroll
    for (int h = 0; h < 32; h++) s += __bfloat162float(p[(size_t)h * 32 * DIM]);
    Ww[((size_t)b * 256 + c) * 32 + w] = s * (1.f / 32.f);
}

// ---------------- circular 32x32 matmuls + bias, writes y (NCHW fp32) -------
__global__ __launch_bounds__(256) void circ_kernel(
    const float* __restrict__ x, const float* __restrict__ Hw,
    const float* __restrict__ Ww, const float* __restrict__ bias,
    float* __restrict__ y)
{
    __shared__ float xs[4][32][36];
    __shared__ float kv[4][32];
    int p0 = blockIdx.x * 4;
    int tid = threadIdx.x;
    int lp = tid >> 6;
    int lt = tid & 63;
    int plane = p0 + lp;
    int b = plane >> 9, c = plane & 511;
    const float* xp = x + (size_t)plane * NPIX;
    for (int idx = lt; idx < NPIX; idx += 64) {
        int r = idx >> 5, cc = idx & 31;
        xs[lp][r][cc] = xp[idx];
    }
    if (lt < 32)
        kv[lp][lt] = (c < 256) ? Hw[((size_t)b * 256 + c) * 32 + lt]
                               : Ww[((size_t)b * 256 + (c - 256)) * 32 + lt];
    __syncthreads();

    int t_r = (lt >> 3) * 4;
    int t_c = (lt & 7) * 4;
    float acc[4][4];
#pragma unroll
    for (int r = 0; r < 4; r++)
#pragma unroll
        for (int cc = 0; cc < 4; cc++) acc[r][cc] = 0.f;
    float bv = bias[c];

    if (c < 256) {
        float kr[32];
#pragma unroll
        for (int u = 0; u < 32; u++) kr[u] = kv[lp][(u - t_r) & 31];
#pragma unroll
        for (int j = 0; j < 32; j++) {
            float4 xv = *(const float4*)&xs[lp][j][t_c];
#pragma unroll
            for (int ri = 0; ri < 4; ri++) {
                float kk = kr[(j - ri) & 31];
                acc[ri][0] += kk * xv.x;
                acc[ri][1] += kk * xv.y;
                acc[ri][2] += kk * xv.z;
                acc[ri][3] += kk * xv.w;
            }
        }
    } else {
        float kr[32];
#pragma unroll
        for (int u = 0; u < 32; u++) kr[u] = kv[lp][(u - t_c) & 31];
#pragma unroll
        for (int j = 0; j < 32; j++) {
            float xv[4];
#pragma unroll
            for (int ri = 0; ri < 4; ri++) xv[ri] = xs[lp][t_r + ri][j];
#pragma unroll
            for (int ci = 0; ci < 4; ci++) {
                float kk = kr[(j - ci) & 31];
#pragma unroll
                for (int ri = 0; ri < 4; ri++) acc[ri][ci] += kk * xv[ri];
            }
        }
    }
    float* yp = y + (size_t)plane * NPIX;
#pragma unroll
    for (int ri = 0; ri < 4; ri++) {
        float4 o;
        o.x = acc[ri][0] + bv; o.y = acc[ri][1] + bv;
        o.z = acc[ri][2] + bv; o.w = acc[ri][3] + bv;
        *(float4*)&yp[(t_r + ri) * 32 + t_c] = o;
    }
}

// ---------------- coalesced two-pass LayerNorm: NCHW fp32 -> token bf16 -----
// grid (8, 16), block 256.  128 tokens/block, 2 threads per token (channel halves)
__global__ __launch_bounds__(256) void ln2_kernel(
    const float* __restrict__ Y, const float* __restrict__ lnw,
    const float* __restrict__ lnb, bf16* __restrict__ O)
{
    __shared__ float mus[128], rss[128];
    __shared__ float ps[256], ps2[256];
    __shared__ float wgt[512], bta[512];
    __shared__ bf16 sm[128][136];
    int chunk = blockIdx.x, b = blockIdx.y;
    int hw0 = chunk * 128;
    int tid = threadIdx.x;
    for (int i = tid; i < 512; i += 256) { wgt[i] = lnw[i]; bta[i] = lnb[i]; }
    int j = tid & 127, half = tid >> 7;
    const float* yb = Y + (size_t)b * DIM * NPIX + hw0 + j;
    float s = 0.f, s2 = 0.f;
    for (int c = half * 256; c < half * 256 + 256; c++) {
        float v = yb[(size_t)c * NPIX];
        s += v; s2 += v * v;
    }
    ps[tid] = s; ps2[tid] = s2;
    __syncthreads();
    if (tid < 128) {
        float S = ps[tid] + ps[tid + 128];
        float S2 = ps2[tid] + ps2[tid + 128];
        float mu = S * (1.f / 512.f);
        float var = S2 * (1.f / 512.f) - mu * mu;
        mus[tid] = mu;
        rss[tid] = rsqrtf(var + 1e-6f);
    }
    __syncthreads();
    float mu = mus[j], rstd = rss[j];
    size_t t0 = (size_t)b * NPIX + hw0;
#pragma unroll
    for (int r = 0; r < 4; r++) {
        int cbase = r * 128 + half * 64;
#pragma unroll 4
        for (int i = 0; i < 64; i++) {
            int c = cbase + i;
            float v = yb[(size_t)c * NPIX];
            float o = (v - mu) * rstd * wgt[c] + bta[c];
            sm[j][half * 64 + i] = __float2bfloat16(o);
        }
        __syncthreads();
        int rt = tid >> 1, u = tid & 1;
        const uint4* src = (const uint4*)&sm[rt][u * 64];
        uint4* dst = (uint4*)&O[(t0 + rt) * DIM + r * 128 + u * 64];
#pragma unroll
        for (int q = 0; q < 8; q++) dst[q] = src[q];
        __syncthreads();
    }
}

__device__ __forceinline__ float gelu_exact(float x) {
    return 0.5f * x * (1.f + erff(x * 0.70710678118654752f));
}

#define BM 128
#define BN 128
#define BKG 32
#define SSTR 48

// GEMM1: C[16384,2048] = gelu(A[16384,512] * W1[2048,512]^T + b)
__global__ __launch_bounds__(256) void gemm1_gelu(
    const bf16* __restrict__ A, const bf16* __restrict__ Bw,
    const float* __restrict__ bias, bf16* __restrict__ C)
{
    const int K = DIM;
    __shared__ bf16 As[BM][SSTR];
    __shared__ bf16 Bs[BN][SSTR];
    int m0 = blockIdx.y * BM, n0 = blockIdx.x * BN;
    int tid = threadIdx.x;
    int wid = tid >> 5, lane = tid & 31;
    int wm = (wid & 1) * 64, wn = (wid >> 1) * 32;
    int g = lane >> 2, tg = lane & 3;
    float acc[4][4][4];
#pragma unroll
    for (int i = 0; i < 4; i++)
#pragma unroll
        for (int j = 0; j < 4; j++)
#pragma unroll
            for (int k = 0; k < 4; k++) acc[i][j][k] = 0.f;

    int lr = tid >> 1, lc = (tid & 1) * 16;
    for (int k0 = 0; k0 < K; k0 += BKG) {
        const bf16* ap = &A[(size_t)(m0 + lr) * K + k0 + lc];
        const bf16* bp = &Bw[(size_t)(n0 + lr) * K + k0 + lc];
        uint4 a0 = *(const uint4*)ap;
        uint4 a1 = *(const uint4*)(ap + 8);
        uint4 b0 = *(const uint4*)bp;
        uint4 b1 = *(const uint4*)(bp + 8);
        *(uint4*)&As[lr][lc]     = a0;
        *(uint4*)&As[lr][lc + 8] = a1;
        *(uint4*)&Bs[lr][lc]     = b0;
        *(uint4*)&Bs[lr][lc + 8] = b1;
        __syncthreads();
#pragma unroll
        for (int ks = 0; ks < 2; ks++) {
            int kb = ks * 16;
            unsigned af[4][4], bfv[4][2];
#pragma unroll
            for (int mi = 0; mi < 4; mi++) {
                int r = wm + mi * 16;
                af[mi][0] = *(const unsigned*)&As[r + g][kb + tg * 2];
                af[mi][1] = *(const unsigned*)&As[r + g + 8][kb + tg * 2];
                af[mi][2] = *(const unsigned*)&As[r + g][kb + tg * 2 + 8];
                af[mi][3] = *(const unsigned*)&As[r + g + 8][kb + tg * 2 + 8];
            }
#pragma unroll
            for (int ni = 0; ni < 4; ni++) {
                int r = wn + ni * 8;
                bfv[ni][0] = *(const unsigned*)&Bs[r + g][kb + tg * 2];
                bfv[ni][1] = *(const unsigned*)&Bs[r + g][kb + tg * 2 + 8];
            }
#pragma unroll
            for (int mi = 0; mi < 4; mi++)
#pragma unroll
                for (int ni = 0; ni < 4; ni++)
                    mma16816(acc[mi][ni], af[mi], bfv[ni]);
        }
        __syncthreads();
    }
#pragma unroll
    for (int mi = 0; mi < 4; mi++)
#pragma unroll
        for (int ni = 0; ni < 4; ni++) {
            int col = n0 + wn + ni * 8 + tg * 2;
            float b0 = bias[col], b1 = bias[col + 1];
            int row0 = m0 + wm + mi * 16 + g;
#pragma unroll
            for (int rr = 0; rr < 2; rr++) {
                int r = row0 + rr * 8;
                float v0 = gelu_exact(acc[mi][ni][rr * 2 + 0] + b0);
                float v1 = gelu_exact(acc[mi][ni][rr * 2 + 1] + b1);
                __nv_bfloat162 p;
                p.x = __float2bfloat16(v0);
                p.y = __float2bfloat16(v1);
                *(__nv_bfloat162*)&C[(size_t)r * FDIM + col] = p;
            }
        }
}

// GEMM2: out = x_in + gamma * (A[16384,2048] * W2[512,2048]^T + b), NCHW write
__global__ __launch_bounds__(256) void gemm2_res(
    const bf16* __restrict__ A, const bf16* __restrict__ Bw,
    const float* __restrict__ bias2, const float* __restrict__ gamma,
    const float* __restrict__ xin, float* __restrict__ out)
{
    const int K = FDIM;
    __shared__ bf16 As[BM][SSTR];
    __shared__ bf16 Bs[BN][SSTR];
    int m0 = blockIdx.y * BM, n0 = blockIdx.x * BN;
    int tid = threadIdx.x;
    int wid = tid >> 5, lane = tid & 31;
    int wm = (wid & 1) * 64, wn = (wid >> 1) * 32;
    int g = lane >> 2, tg = lane & 3;
    float acc[4][4][4];
#pragma unroll
    for (int i = 0; i < 4; i++)
#pragma unroll
        for (int j = 0; j < 4; j++)
#pragma unroll
            for (int k = 0; k < 4; k++) acc[i][j][k] = 0.f;

    int lr = tid >> 1, lc = (tid & 1) * 16;
    for (int k0 = 0; k0 < K; k0 += BKG) {
        const bf16* ap = &A[(size_t)(m0 + lr) * K + k0 + lc];
        const bf16* bp = &Bw[(size_t)(n0 + lr) * K + k0 + lc];
        uint4 a0 = *(const uint4*)ap;
        uint4 a1 = *(const uint4*)(ap + 8);
        uint4 b0 = *(const uint4*)bp;
        uint4 b1 = *(const uint4*)(bp + 8);
        *(uint4*)&As[lr][lc]     = a0;
        *(uint4*)&As[lr][lc + 8] = a1;
        *(uint4*)&Bs[lr][lc]     = b0;
        *(uint4*)&Bs[lr][lc + 8] = b1;
        __syncthreads();
#pragma unroll
        for (int ks = 0; ks < 2; ks++) {
            int kb = ks * 16;
            unsigned af[4][4], bfv[4][2];
#pragma unroll
            for (int mi = 0; mi < 4; mi++) {
                int r = wm + mi * 16;
                af[mi][0] = *(const unsigned*)&As[r + g][kb + tg * 2];
                af[mi][1] = *(const unsigned*)&As[r + g + 8][kb + tg * 2];
                af[mi][2] = *(const unsigned*)&As[r + g][kb + tg * 2 + 8];
                af[mi][3] = *(const unsigned*)&As[r + g + 8][kb + tg * 2 + 8];
            }
#pragma unroll
            for (int ni = 0; ni < 4; ni++) {
                int r = wn + ni * 8;
                bfv[ni][0] = *(const unsigned*)&Bs[r + g][kb + tg * 2];
                bfv[ni][1] = *(const unsigned*)&Bs[r + g][kb + tg * 2 + 8];
            }
#pragma unroll
            for (int mi = 0; mi < 4; mi++)
#pragma unroll
                for (int ni = 0; ni < 4; ni++)
                    mma16816(acc[mi][ni], af[mi], bfv[ni]);
        }
        __syncthreads();
    }
#pragma unroll
    for (int mi = 0; mi < 4; mi++)
#pragma unroll
        for (int ni = 0; ni < 4; ni++) {
            int col = n0 + wn + ni * 8 + tg * 2;
            float gb0 = gamma[col], gb1 = gamma[col + 1];
            float bb0 = bias2[col], bb1 = bias2[col + 1];
            int row0 = m0 + wm + mi * 16 + g;
#pragma unroll
            for (int rr = 0; rr < 2; rr++) {
                int r = row0 + rr * 8;
                int bI = r >> 10, hw = r & 1023;
                size_t i0 = ((size_t)bI * DIM + col) * NPIX + hw;
                size_t i1 = i0 + NPIX;
                out[i0] = xin[i0] + gb0 * (acc[mi][ni][rr * 2 + 0] + bb0);
                out[i1] = xin[i1] + gb1 * (acc[mi][ni][rr * 2 + 1] + bb1);
            }
        }
}

// ---------------- host launcher ----------------
extern "C" void kernel_launch(void* const* d_in, const int* in_sizes, int n_in,
                              void* d_out, int out_size)
{
    const float* x      = (const float*)d_in[0];
    const float* pe_w1  = (const float*)d_in[1];
    const float* pe_bng = (const float*)d_in[2];
    const float* pe_bnb = (const float*)d_in[3];
    const float* pe_bnm = (const float*)d_in[4];
    const float* pe_bnv = (const float*)d_in[5];
    const float* pe_w2  = (const float*)d_in[6];
    const float* pe_b2  = (const float*)d_in[7];
    const float* kg_w1  = (const float*)d_in[8];
    const float* kg_bng = (const float*)d_in[9];
    const float* kg_bnb = (const float*)d_in[10];
    const float* kg_bnm = (const float*)d_in[11];
    const float* kg_bnv = (const float*)d_in[12];
    const float* kg_w2  = (const float*)d_in[13];
    const float* kg_b2  = (const float*)d_in[14];
    const float* bias   = (const float*)d_in[15];
    const float* ln_w   = (const float*)d_in[16];
    const float* ln_b   = (const float*)d_in[17];
    const float* pw1_w  = (const float*)d_in[18];
    const float* pw1_b  = (const float*)d_in[19];
    const float* pw2_w  = (const float*)d_in[20];
    const float* pw2_b  = (const float*)d_in[21];
    const float* gamma  = (const float*)d_in[22];
    float* outp = (float*)d_out;

    bf16 *pxtok, *pxtok2, *phtok, *pkwtok, *pybf, *pmid, *pw1bf, *pw2bf;
    bf16 *pw1pe, *pw1kg, *pw2pe, *pw2kg;
    float *pxp, *py, *pHw, *pWw;
    cudaGetSymbolAddress((void**)&pxtok,  g_xtok);
    cudaGetSymbolAddress((void**)&pxtok2, g_xtok2);
    cudaGetSymbolAddress((void**)&phtok,  g_htok);
    cudaGetSymbolAddress((void**)&pkwtok, g_kwtok);
    cudaGetSymbolAddress((void**)&pxp, g_xp);
    cudaGetSymbolAddress((void**)&py,  g_y);
    cudaGetSymbolAddress((void**)&pHw, g_Hw);
    cudaGetSymbolAddress((void**)&pWw, g_Ww);
    cudaGetSymbolAddress((void**)&pybf,  g_ybf);
    cudaGetSymbolAddress((void**)&pmid,  g_mid);
    cudaGetSymbolAddress((void**)&pw1bf, g_w1bf);
    cudaGetSymbolAddress((void**)&pw2bf, g_w2bf);
    cudaGetSymbolAddress((void**)&pw1pe, g_w1pe);
    cudaGetSymbolAddress((void**)&pw1kg, g_w1kg);
    cudaGetSymbolAddress((void**)&pw2pe, g_w2pe);
    cudaGetSymbolAddress((void**)&pw2kg, g_w2kg);

    // weight conversions
    cvt_weights<<<(FDIM * DIM + 255) / 256, 256>>>(pw1_w, pw2_w, pw1bf, pw2bf);
    cvt_convw<<<(MIDC * DIM * 9 + 255) / 256, 256>>>(pe_w1, kg_w1, pe_w2, kg_w2,
                                                     pw1pe, pw1kg, pw2pe, pw2kg);
    // x -> tokens
    nchw2tok<<<dim3(8, 4, BATCH), 256>>>(x, pxtok);

    // pe branch
    conv1_tok<<<NTOK / 64, 256>>>(pxtok, pw1pe, pe_bng, pe_bnb, pe_bnm, pe_bnv, phtok);
    conv2_tok<<<dim3(8, NTOK / 128), 256>>>(phtok, pw2pe, pe_b2, pxtok, pxtok2);
    // kg branch
    conv1_tok<<<NTOK / 64, 256>>>(pxtok2, pw1kg, kg_bng, kg_bnb, kg_bnm, kg_bnv, phtok);
    conv2_tok<<<dim3(8, NTOK / 128), 256>>>(phtok, pw2kg, kg_b2, nullptr, pkwtok);

    // x planes for circular mixing
    tok2nchw<<<dim3(8, 4, BATCH), 256>>>(pxtok2, pxp);

    // mean reductions
    reduceH_tok<<<dim3(32, BATCH), 256>>>(pkwtok, pHw);
    reduceW_tok<<<dim3(32, BATCH), 256>>>(pkwtok, pWw);

    // circular mixing + bias
    circ_kernel<<<(BATCH * DIM) / 4, 256>>>(pxp, pHw, pWw, bias, py);

    // layernorm -> bf16 tokens
    ln2_kernel<<<dim3(8, BATCH), 256>>>(py, ln_w, ln_b, pybf);

    // MLP
    gemm1_gelu<<<dim3(FDIM / BN, NTOK / BM), 256>>>(pybf, pw1bf, pw1_b, pmid);
    gemm2_res<<<dim3(DIM / BN, NTOK / BM), 256>>>(pmid, pw2bf, pw2_b, gamma, x, outp);
}

// round 4
// speedup vs baseline: 2.6724x; 1.4020x over previous
#include <cuda_runtime.h>
#include <cuda_bf16.h>
#include <math.h>

#define BATCH 16
#define DIM 512
#define MIDC 32
#define NPIX 1024
#define NTOK 16384
#define FDIM 2048

typedef __nv_bfloat16 bf16;

// ---------------- scratch (static device memory) ----------------
__device__ bf16 g_xtok [NTOK * DIM];
__device__ bf16 g_xtok2[NTOK * DIM];
__device__ bf16 g_htok [NTOK * MIDC];
__device__ bf16 g_kwtok[NTOK * DIM];
__device__ float g_xp[BATCH * DIM * NPIX];
__device__ float g_y [BATCH * DIM * NPIX];
__device__ float g_Hw[BATCH * 256 * 32];
__device__ float g_Ww[BATCH * 256 * 32];
__device__ bf16 g_ybf[NTOK * DIM];
__device__ bf16 g_mid[NTOK * FDIM];
__device__ bf16 g_w1bf[FDIM * DIM];
__device__ bf16 g_w2bf[DIM * FDIM];
__device__ bf16 g_w1pe[9 * MIDC * DIM];
__device__ bf16 g_w1kg[9 * MIDC * DIM];
__device__ bf16 g_w2pe[9 * DIM * MIDC];
__device__ bf16 g_w2kg[9 * DIM * MIDC];

// ---------------- cp.async helpers ----------------
__device__ __forceinline__ void cp16(void* s, const void* g) {
    unsigned sa = (unsigned)__cvta_generic_to_shared(s);
    asm volatile("cp.async.cg.shared.global [%0], [%1], 16;\n" :: "r"(sa), "l"(g));
}
__device__ __forceinline__ void cp16p(void* s, const void* g, bool pred) {
    unsigned sa = (unsigned)__cvta_generic_to_shared(s);
    int sz = pred ? 16 : 0;
    asm volatile("cp.async.cg.shared.global [%0], [%1], 16, %2;\n" :: "r"(sa), "l"(g), "r"(sz));
}
#define CP_COMMIT() asm volatile("cp.async.commit_group;\n")
#define CP_WAIT(n)  asm volatile("cp.async.wait_group %0;\n" :: "n"(n))

// ---------------- weight conversions ----------------
__global__ void cvt_weights(const float* __restrict__ w1, const float* __restrict__ w2,
                            bf16* __restrict__ o1, bf16* __restrict__ o2)
{
    int i = blockIdx.x * blockDim.x + threadIdx.x;
    if (i < FDIM * DIM) {
        o1[i] = __float2bfloat16(w1[i]);
        o2[i] = __float2bfloat16(w2[i]);
    }
}

__global__ void cvt_convw(const float* __restrict__ pw1, const float* __restrict__ kw1,
                          const float* __restrict__ pw2, const float* __restrict__ kw2,
                          bf16* __restrict__ o1p, bf16* __restrict__ o1k,
                          bf16* __restrict__ o2p, bf16* __restrict__ o2k)
{
    int i = blockIdx.x * blockDim.x + threadIdx.x;
    if (i >= MIDC * DIM * 9) return;
    int off = i % 9;
    int ic = (i / 9) % DIM, oc = i / (9 * DIM);
    o1p[(off * MIDC + oc) * DIM + ic] = __float2bfloat16(pw1[i]);
    o1k[(off * MIDC + oc) * DIM + ic] = __float2bfloat16(kw1[i]);
    int ic2 = (i / 9) % MIDC, oc2 = i / (9 * MIDC);
    o2p[(off * DIM + oc2) * MIDC + ic2] = __float2bfloat16(pw2[i]);
    o2k[(off * DIM + oc2) * MIDC + ic2] = __float2bfloat16(kw2[i]);
}

// ---------------- NCHW fp32 -> token bf16 transpose ----------------
__global__ __launch_bounds__(256) void nchw2tok(const float* __restrict__ X, bf16* __restrict__ T)
{
    __shared__ bf16 sm[128][136];
    int hw0 = blockIdx.x * 128, c0 = blockIdx.y * 128, b = blockIdx.z;
    int tid = threadIdx.x;
    const float* xp = X + ((size_t)b * DIM + c0) * NPIX + hw0;
#pragma unroll
    for (int i = 0; i < 16; i++) {
        int idx = tid + i * 256;
        int rc = idx >> 5, u = idx & 31;
        float4 v = *(const float4*)&xp[(size_t)rc * NPIX + u * 4];
        union { uint2 q; bf16 h[4]; } pk;
        pk.h[0] = __float2bfloat16(v.x); pk.h[1] = __float2bfloat16(v.y);
        pk.h[2] = __float2bfloat16(v.z); pk.h[3] = __float2bfloat16(v.w);
        *(uint2*)&sm[rc][u * 4] = pk.q;
    }
    __syncthreads();
    bf16* tp = T + ((size_t)(b * NPIX + hw0)) * DIM + c0;
#pragma unroll
    for (int i = 0; i < 8; i++) {
        int idx = tid + i * 256;
        int rt = idx >> 4, uu = idx & 15;
        union { uint4 q; bf16 h[8]; } pk;
#pragma unroll
        for (int j = 0; j < 8; j++) pk.h[j] = sm[uu * 8 + j][rt];
        *(uint4*)&tp[(size_t)rt * DIM + uu * 8] = pk.q;
    }
}

// ---------------- token bf16 -> NCHW fp32 transpose ----------------
__global__ __launch_bounds__(256) void tok2nchw(const bf16* __restrict__ T, float* __restrict__ X)
{
    __shared__ bf16 sm[128][136];
    int hw0 = blockIdx.x * 128, c0 = blockIdx.y * 128, b = blockIdx.z;
    int tid = threadIdx.x;
    const bf16* tp = T + ((size_t)(b * NPIX + hw0)) * DIM + c0;
#pragma unroll
    for (int i = 0; i < 8; i++) {
        int idx = tid + i * 256;
        int rt = idx >> 4, uu = idx & 15;
        *(uint4*)&sm[rt][uu * 8] = *(const uint4*)&tp[(size_t)rt * DIM + uu * 8];
    }
    __syncthreads();
    float* xp = X + ((size_t)b * DIM + c0) * NPIX + hw0;
#pragma unroll
    for (int i = 0; i < 16; i++) {
        int idx = tid + i * 256;
        int rc = idx >> 5, u = idx & 31;
        float4 v;
        v.x = __bfloat162float(sm[u * 4 + 0][rc]);
        v.y = __bfloat162float(sm[u * 4 + 1][rc]);
        v.z = __bfloat162float(sm[u * 4 + 2][rc]);
        v.w = __bfloat162float(sm[u * 4 + 3][rc]);
        *(float4*)&xp[(size_t)rc * NPIX + u * 4] = v;
    }
}

// ---------------- MMA helper ----------------
__device__ __forceinline__ void mma16816(float* d, const unsigned* a, const unsigned* b) {
    asm volatile(
        "mma.sync.aligned.m16n8k16.row.col.f32.bf16.bf16.f32 "
        "{%0,%1,%2,%3}, {%4,%5,%6,%7}, {%8,%9}, {%0,%1,%2,%3};\n"
        : "+f"(d[0]), "+f"(d[1]), "+f"(d[2]), "+f"(d[3])
        : "r"(a[0]), "r"(a[1]), "r"(a[2]), "r"(a[3]), "r"(b[0]), "r"(b[1]));
}

// ---------------- conv1 implicit GEMM (double-buffered cp.async) ------------
// M tile 64, N=32, K = 9 offsets x 512 (72 k-tiles of 64)
#define C1S 72
__global__ __launch_bounds__(256) void conv1_tok(
    const bf16* __restrict__ X, const bf16* __restrict__ W,
    const float* __restrict__ bng, const float* __restrict__ bnb,
    const float* __restrict__ bnm, const float* __restrict__ bnv,
    bf16* __restrict__ O)
{
    __shared__ bf16 As[2][64][C1S];
    __shared__ bf16 Bs[2][32][C1S];
    __shared__ bf16 Cs[64][48];
    __shared__ float sS[32], sT[32];
    int m0 = blockIdx.x * 64;
    int tid = threadIdx.x;
    if (tid < 32) {
        float inv = rsqrtf(bnv[tid] + 1e-5f);
        float s = bng[tid] * inv;
        sS[tid] = s;
        sT[tid] = bnb[tid] - bnm[tid] * s;
    }
    int ar = tid >> 2, aq = (tid & 3) * 16;
    int t = m0 + ar;
    int th = (t >> 5) & 31, tw = t & 31;
    int br = tid >> 3, bq = (tid & 7) * 8;
    int wid = tid >> 5, lane = tid & 31;
    int wm = (wid & 3) * 16, wn = (wid >> 2) * 16;
    int g = lane >> 2, tg = lane & 3;

    float acc[2][4];
#pragma unroll
    for (int i = 0; i < 2; i++)
#pragma unroll
        for (int j = 0; j < 4; j++) acc[i][j] = 0.f;

    auto load_tile = [&](int kt, int buf) {
        int off = kt >> 3, k0 = (kt & 7) * 64;
        int dy = off / 3 - 1, dx = off % 3 - 1;
        bool valid = ((unsigned)(th + dy) < 32u) && ((unsigned)(tw + dx) < 32u);
        const bf16* srcA = X + ((long)(t + dy * 32 + dx)) * DIM + k0 + aq;
        cp16p(&As[buf][ar][aq], srcA, valid);
        cp16p(&As[buf][ar][aq + 8], srcA + 8, valid);
        const bf16* srcB = W + (size_t)(off * MIDC + br) * DIM + k0 + bq;
        cp16(&Bs[buf][br][bq], srcB);
    };

    load_tile(0, 0);
    CP_COMMIT();
    for (int kt = 0; kt < 72; kt++) {
        int buf = kt & 1;
        if (kt < 71) {
            load_tile(kt + 1, buf ^ 1);
            CP_COMMIT();
            CP_WAIT(1);
        } else {
            CP_WAIT(0);
        }
        __syncthreads();
#pragma unroll
        for (int kc = 0; kc < 4; kc++) {
            int kb = kc * 16;
            unsigned a[4], bfr[2][2];
            a[0] = *(const unsigned*)&As[buf][wm + g][kb + tg * 2];
            a[1] = *(const unsigned*)&As[buf][wm + g + 8][kb + tg * 2];
            a[2] = *(const unsigned*)&As[buf][wm + g][kb + tg * 2 + 8];
            a[3] = *(const unsigned*)&As[buf][wm + g + 8][kb + tg * 2 + 8];
#pragma unroll
            for (int ni = 0; ni < 2; ni++) {
                bfr[ni][0] = *(const unsigned*)&Bs[buf][wn + ni * 8 + g][kb + tg * 2];
                bfr[ni][1] = *(const unsigned*)&Bs[buf][wn + ni * 8 + g][kb + tg * 2 + 8];
            }
            mma16816(acc[0], a, bfr[0]);
            mma16816(acc[1], a, bfr[1]);
        }
        __syncthreads();
    }
#pragma unroll
    for (int ni = 0; ni < 2; ni++)
#pragma unroll
        for (int rr = 0; rr < 2; rr++)
#pragma unroll
            for (int j = 0; j < 2; j++) {
                int col = wn + ni * 8 + tg * 2 + j;
                int row = wm + g + rr * 8;
                float v = acc[ni][rr * 2 + j] * sS[col] + sT[col];
                Cs[row][col] = __float2bfloat16(fmaxf(v, 0.f));
            }
    __syncthreads();
    int orow = tid >> 2, oq = (tid & 3) * 8;
    *(uint4*)&O[(size_t)(m0 + orow) * MIDC + oq] = *(uint4*)&Cs[orow][oq];
}

// ---------------- conv2 implicit GEMM (double-buffered cp.async) ------------
// M tile 128, N tile 64, K = 9 x 32
__global__ __launch_bounds__(256) void conv2_tok(
    const bf16* __restrict__ Hx, const bf16* __restrict__ W,
    const float* __restrict__ b2, const bf16* __restrict__ res,
    bf16* __restrict__ O)
{
    __shared__ bf16 As[2][128][40];
    __shared__ bf16 Bs[2][64][40];
    int n0 = blockIdx.x * 64, m0 = blockIdx.y * 128;
    int tid = threadIdx.x;
    int ar = tid >> 1, aq = (tid & 1) * 16;
    int t = m0 + ar;
    int th = (t >> 5) & 31, tw = t & 31;
    int br = tid >> 2, bq = (tid & 3) * 8;
    int wid = tid >> 5, lane = tid & 31;
    int wm = (wid & 3) * 32, wn = (wid >> 2) * 32;
    int g = lane >> 2, tg = lane & 3;

    float acc[2][4][4];
#pragma unroll
    for (int i = 0; i < 2; i++)
#pragma unroll
        for (int j = 0; j < 4; j++)
#pragma unroll
            for (int k = 0; k < 4; k++) acc[i][j][k] = 0.f;

    auto load_tile = [&](int off, int buf) {
        int dy = off / 3 - 1, dx = off % 3 - 1;
        bool valid = ((unsigned)(th + dy) < 32u) && ((unsigned)(tw + dx) < 32u);
        const bf16* srcA = Hx + ((long)(t + dy * 32 + dx)) * MIDC + aq;
        cp16p(&As[buf][ar][aq], srcA, valid);
        cp16p(&As[buf][ar][aq + 8], srcA + 8, valid);
        cp16(&Bs[buf][br][bq], &W[(size_t)(off * DIM + n0 + br) * MIDC + bq]);
    };

    load_tile(0, 0);
    CP_COMMIT();
    for (int off = 0; off < 9; off++) {
        int buf = off & 1;
        if (off < 8) {
            load_tile(off + 1, buf ^ 1);
            CP_COMMIT();
            CP_WAIT(1);
        } else {
            CP_WAIT(0);
        }
        __syncthreads();
#pragma unroll
        for (int kc = 0; kc < 2; kc++) {
            int kb = kc * 16;
            unsigned a[2][4], bfr[4][2];
#pragma unroll
            for (int mi = 0; mi < 2; mi++) {
                int r = wm + mi * 16;
                a[mi][0] = *(const unsigned*)&As[buf][r + g][kb + tg * 2];
                a[mi][1] = *(const unsigned*)&As[buf][r + g + 8][kb + tg * 2];
                a[mi][2] = *(const unsigned*)&As[buf][r + g][kb + tg * 2 + 8];
                a[mi][3] = *(const unsigned*)&As[buf][r + g + 8][kb + tg * 2 + 8];
            }
#pragma unroll
            for (int ni = 0; ni < 4; ni++) {
                bfr[ni][0] = *(const unsigned*)&Bs[buf][wn + ni * 8 + g][kb + tg * 2];
                bfr[ni][1] = *(const unsigned*)&Bs[buf][wn + ni * 8 + g][kb + tg * 2 + 8];
            }
#pragma unroll
            for (int mi = 0; mi < 2; mi++)
#pragma unroll
                for (int ni = 0; ni < 4; ni++)
                    mma16816(acc[mi][ni], a[mi], bfr[ni]);
        }
        __syncthreads();
    }
    float bv0[4], bv1[4];
#pragma unroll
    for (int ni = 0; ni < 4; ni++) {
        int col = n0 + wn + ni * 8 + tg * 2;
        bv0[ni] = b2[col];
        bv1[ni] = b2[col + 1];
    }
#pragma unroll
    for (int mi = 0; mi < 2; mi++)
#pragma unroll
        for (int ni = 0; ni < 4; ni++)
#pragma unroll
            for (int rr = 0; rr < 2; rr++) {
                int row = m0 + wm + mi * 16 + g + rr * 8;
                size_t ad = (size_t)row * DIM + n0 + wn + ni * 8 + tg * 2;
                float v0 = acc[mi][ni][rr * 2 + 0] + bv0[ni];
                float v1 = acc[mi][ni][rr * 2 + 1] + bv1[ni];
                if (res) {
                    __nv_bfloat162 rv = *(const __nv_bfloat162*)&res[ad];
                    v0 += __bfloat162float(rv.x);
                    v1 += __bfloat162float(rv.y);
                }
                __nv_bfloat162 p;
                p.x = __float2bfloat16(v0);
                p.y = __float2bfloat16(v1);
                *(__nv_bfloat162*)&O[ad] = p;
            }
}

// ---------------- fused mean reductions (H and W halves) --------------------
// grid(32,16), block 512: t<256 -> H (h=blockIdx.x), t>=256 -> W (w=blockIdx.x)
__global__ __launch_bounds__(512) void reduce_tok(const bf16* __restrict__ T,
                                                  float* __restrict__ Hw,
                                                  float* __restrict__ Ww)
{
    int q = blockIdx.x, b = blockIdx.y;
    int tid = threadIdx.x;
    if (tid < 256) {
        int c = tid;
        const bf16* p = T + (size_t)(b * NPIX + q * 32) * DIM + c;
        float s = 0.f;
#pragma unroll
        for (int w = 0; w < 32; w++) s += __bfloat162float(p[(size_t)w * DIM]);
        Hw[((size_t)b * 256 + c) * 32 + q] = s * (1.f / 32.f);
    } else {
        int c = tid - 256;
        const bf16* p = T + (size_t)(b * NPIX + q) * DIM + 256 + c;
        float s = 0.f;
#pragma unroll
        for (int h = 0; h < 32; h++) s += __bfloat162float(p[(size_t)h * 32 * DIM]);
        Ww[((size_t)b * 256 + c) * 32 + q] = s * (1.f / 32.f);
    }
}

// ---------------- circular 32x32 matmuls + bias, writes y (NCHW fp32) -------
__global__ __launch_bounds__(256) void circ_kernel(
    const float* __restrict__ x, const float* __restrict__ Hw,
    const float* __restrict__ Ww, const float* __restrict__ bias,
    float* __restrict__ y)
{
    __shared__ float xs[4][32][36];
    __shared__ float kv[4][32];
    int p0 = blockIdx.x * 4;
    int tid = threadIdx.x;
    int lp = tid >> 6;
    int lt = tid & 63;
    int plane = p0 + lp;
    int b = plane >> 9, c = plane & 511;
    const float* xp = x + (size_t)plane * NPIX;
    for (int idx = lt; idx < NPIX; idx += 64) {
        int r = idx >> 5, cc = idx & 31;
        xs[lp][r][cc] = xp[idx];
    }
    if (lt < 32)
        kv[lp][lt] = (c < 256) ? Hw[((size_t)b * 256 + c) * 32 + lt]
                               : Ww[((size_t)b * 256 + (c - 256)) * 32 + lt];
    __syncthreads();

    int t_r = (lt >> 3) * 4;
    int t_c = (lt & 7) * 4;
    float acc[4][4];
#pragma unroll
    for (int r = 0; r < 4; r++)
#pragma unroll
        for (int cc = 0; cc < 4; cc++) acc[r][cc] = 0.f;
    float bv = bias[c];

    if (c < 256) {
        float kr[32];
#pragma unroll
        for (int u = 0; u < 32; u++) kr[u] = kv[lp][(u - t_r) & 31];
#pragma unroll
        for (int j = 0; j < 32; j++) {
            float4 xv = *(const float4*)&xs[lp][j][t_c];
#pragma unroll
            for (int ri = 0; ri < 4; ri++) {
                float kk = kr[(j - ri) & 31];
                acc[ri][0] += kk * xv.x;
                acc[ri][1] += kk * xv.y;
                acc[ri][2] += kk * xv.z;
                acc[ri][3] += kk * xv.w;
            }
        }
    } else {
        float kr[32];
#pragma unroll
        for (int u = 0; u < 32; u++) kr[u] = kv[lp][(u - t_c) & 31];
#pragma unroll
        for (int j = 0; j < 32; j++) {
            float xv[4];
#pragma unroll
            for (int ri = 0; ri < 4; ri++) xv[ri] = xs[lp][t_r + ri][j];
#pragma unroll
            for (int ci = 0; ci < 4; ci++) {
                float kk = kr[(j - ci) & 31];
#pragma unroll
                for (int ri = 0; ri < 4; ri++) acc[ri][ci] += kk * xv[ri];
            }
        }
    }
    float* yp = y + (size_t)plane * NPIX;
#pragma unroll
    for (int ri = 0; ri < 4; ri++) {
        float4 o;
        o.x = acc[ri][0] + bv; o.y = acc[ri][1] + bv;
        o.z = acc[ri][2] + bv; o.w = acc[ri][3] + bv;
        *(float4*)&yp[(t_r + ri) * 32 + t_c] = o;
    }
}

// ---------------- coalesced two-pass LayerNorm: NCHW fp32 -> token bf16 -----
__global__ __launch_bounds__(256) void ln2_kernel(
    const float* __restrict__ Y, const float* __restrict__ lnw,
    const float* __restrict__ lnb, bf16* __restrict__ O)
{
    __shared__ float mus[128], rss[128];
    __shared__ float ps[256], ps2[256];
    __shared__ float wgt[512], bta[512];
    __shared__ bf16 sm[128][136];
    int chunk = blockIdx.x, b = blockIdx.y;
    int hw0 = chunk * 128;
    int tid = threadIdx.x;
    for (int i = tid; i < 512; i += 256) { wgt[i] = lnw[i]; bta[i] = lnb[i]; }
    int j = tid & 127, half = tid >> 7;
    const float* yb = Y + (size_t)b * DIM * NPIX + hw0 + j;
    float s = 0.f, s2 = 0.f;
    for (int c = half * 256; c < half * 256 + 256; c++) {
        float v = yb[(size_t)c * NPIX];
        s += v; s2 += v * v;
    }
    ps[tid] = s; ps2[tid] = s2;
    __syncthreads();
    if (tid < 128) {
        float S = ps[tid] + ps[tid + 128];
        float S2 = ps2[tid] + ps2[tid + 128];
        float mu = S * (1.f / 512.f);
        float var = S2 * (1.f / 512.f) - mu * mu;
        mus[tid] = mu;
        rss[tid] = rsqrtf(var + 1e-6f);
    }
    __syncthreads();
    float mu = mus[j], rstd = rss[j];
    size_t t0 = (size_t)b * NPIX + hw0;
#pragma unroll
    for (int r = 0; r < 4; r++) {
        int cbase = r * 128 + half * 64;
#pragma unroll 4
        for (int i = 0; i < 64; i++) {
            int c = cbase + i;
            float v = yb[(size_t)c * NPIX];
            float o = (v - mu) * rstd * wgt[c] + bta[c];
            sm[j][half * 64 + i] = __float2bfloat16(o);
        }
        __syncthreads();
        int rt = tid >> 1, u = tid & 1;
        const uint4* src = (const uint4*)&sm[rt][u * 64];
        uint4* dst = (uint4*)&O[(t0 + rt) * DIM + r * 128 + u * 64];
#pragma unroll
        for (int q = 0; q < 8; q++) dst[q] = src[q];
        __syncthreads();
    }
}

__device__ __forceinline__ float gelu_exact(float x) {
    return 0.5f * x * (1.f + erff(x * 0.70710678118654752f));
}

#define BM 128
#define BN 128
#define SSTR 40

// GEMM1: C[16384,2048] = gelu(A[16384,512] * W1[2048,512]^T + b)  (2-stage)
__global__ __launch_bounds__(256) void gemm1_gelu(
    const bf16* __restrict__ A, const bf16* __restrict__ Bw,
    const float* __restrict__ bias, bf16* __restrict__ C)
{
    const int K = DIM, KT = K / 32;
    __shared__ bf16 As[2][BM][SSTR];
    __shared__ bf16 Bs[2][BN][SSTR];
    int m0 = blockIdx.y * BM, n0 = blockIdx.x * BN;
    int tid = threadIdx.x;
    int wid = tid >> 5, lane = tid & 31;
    int wm = (wid & 1) * 64, wn = (wid >> 1) * 32;
    int g = lane >> 2, tg = lane & 3;
    float acc[4][4][4];
#pragma unroll
    for (int i = 0; i < 4; i++)
#pragma unroll
        for (int j = 0; j < 4; j++)
#pragma unroll
            for (int k = 0; k < 4; k++) acc[i][j][k] = 0.f;

    int lr = tid >> 1, lc = (tid & 1) * 16;
    const bf16* apb = &A[(size_t)(m0 + lr) * K + lc];
    const bf16* bpb = &Bw[(size_t)(n0 + lr) * K + lc];

    auto load_tile = [&](int kt, int buf) {
        cp16(&As[buf][lr][lc],     apb + kt * 32);
        cp16(&As[buf][lr][lc + 8], apb + kt * 32 + 8);
        cp16(&Bs[buf][lr][lc],     bpb + kt * 32);
        cp16(&Bs[buf][lr][lc + 8], bpb + kt * 32 + 8);
    };

    load_tile(0, 0);
    CP_COMMIT();
    for (int kt = 0; kt < KT; kt++) {
        int buf = kt & 1;
        if (kt + 1 < KT) {
            load_tile(kt + 1, buf ^ 1);
            CP_COMMIT();
            CP_WAIT(1);
        } else {
            CP_WAIT(0);
        }
        __syncthreads();
#pragma unroll
        for (int ks = 0; ks < 2; ks++) {
            int kb = ks * 16;
            unsigned af[4][4], bfv[4][2];
#pragma unroll
            for (int mi = 0; mi < 4; mi++) {
                int r = wm + mi * 16;
                af[mi][0] = *(const unsigned*)&As[buf][r + g][kb + tg * 2];
                af[mi][1] = *(const unsigned*)&As[buf][r + g + 8][kb + tg * 2];
                af[mi][2] = *(const unsigned*)&As[buf][r + g][kb + tg * 2 + 8];
                af[mi][3] = *(const unsigned*)&As[buf][r + g + 8][kb + tg * 2 + 8];
            }
#pragma unroll
            for (int ni = 0; ni < 4; ni++) {
                int r = wn + ni * 8;
                bfv[ni][0] = *(const unsigned*)&Bs[buf][r + g][kb + tg * 2];
                bfv[ni][1] = *(const unsigned*)&Bs[buf][r + g][kb + tg * 2 + 8];
            }
#pragma unroll
            for (int mi = 0; mi < 4; mi++)
#pragma unroll
                for (int ni = 0; ni < 4; ni++)
                    mma16816(acc[mi][ni], af[mi], bfv[ni]);
        }
        __syncthreads();
    }
#pragma unroll
    for (int mi = 0; mi < 4; mi++)
#pragma unroll
        for (int ni = 0; ni < 4; ni++) {
            int col = n0 + wn + ni * 8 + tg * 2;
            float b0 = bias[col], b1 = bias[col + 1];
            int row0 = m0 + wm + mi * 16 + g;
#pragma unroll
            for (int rr = 0; rr < 2; rr++) {
                int r = row0 + rr * 8;
                float v0 = gelu_exact(acc[mi][ni][rr * 2 + 0] + b0);
                float v1 = gelu_exact(acc[mi][ni][rr * 2 + 1] + b1);
                __nv_bfloat162 p;
                p.x = __float2bfloat16(v0);
                p.y = __float2bfloat16(v1);
                *(__nv_bfloat162*)&C[(size_t)r * FDIM + col] = p;
            }
        }
}

// GEMM2: out = x_in + gamma*(A[16384,2048]*W2[512,2048]^T + b), coalesced NCHW
__global__ __launch_bounds__(256) void gemm2_res(
    const bf16* __restrict__ A, const bf16* __restrict__ Bw,
    const float* __restrict__ bias2, const float* __restrict__ gamma,
    const float* __restrict__ xin, float* __restrict__ out)
{
    const int K = FDIM, KT = K / 32;
    __shared__ __align__(16) char sm_raw[2 * BM * SSTR * 2 + 2 * BN * SSTR * 2];
    bf16 (*As)[BM][SSTR] = (bf16(*)[BM][SSTR])sm_raw;
    bf16 (*Bs)[BN][SSTR] = (bf16(*)[BN][SSTR])(sm_raw + 2 * BM * SSTR * 2);
    int m0 = blockIdx.y * BM, n0 = blockIdx.x * BN;
    int tid = threadIdx.x;
    int wid = tid >> 5, lane = tid & 31;
    int wm = (wid & 1) * 64, wn = (wid >> 1) * 32;
    int g = lane >> 2, tg = lane & 3;
    float acc[4][4][4];
#pragma unroll
    for (int i = 0; i < 4; i++)
#pragma unroll
        for (int j = 0; j < 4; j++)
#pragma unroll
            for (int k = 0; k < 4; k++) acc[i][j][k] = 0.f;

    int lr = tid >> 1, lc = (tid & 1) * 16;
    const bf16* apb = &A[(size_t)(m0 + lr) * K + lc];
    const bf16* bpb = &Bw[(size_t)(n0 + lr) * K + lc];

    auto load_tile = [&](int kt, int buf) {
        cp16(&As[buf][lr][lc],     apb + kt * 32);
        cp16(&As[buf][lr][lc + 8], apb + kt * 32 + 8);
        cp16(&Bs[buf][lr][lc],     bpb + kt * 32);
        cp16(&Bs[buf][lr][lc + 8], bpb + kt * 32 + 8);
    };

    load_tile(0, 0);
    CP_COMMIT();
    for (int kt = 0; kt < KT; kt++) {
        int buf = kt & 1;
        if (kt + 1 < KT) {
            load_tile(kt + 1, buf ^ 1);
            CP_COMMIT();
            CP_WAIT(1);
        } else {
            CP_WAIT(0);
        }
        __syncthreads();
#pragma unroll
        for (int ks = 0; ks < 2; ks++) {
            int kb = ks * 16;
            unsigned af[4][4], bfv[4][2];
#pragma unroll
            for (int mi = 0; mi < 4; mi++) {
                int r = wm + mi * 16;
                af[mi][0] = *(const unsigned*)&As[buf][r + g][kb + tg * 2];
                af[mi][1] = *(const unsigned*)&As[buf][r + g + 8][kb + tg * 2];
                af[mi][2] = *(const unsigned*)&As[buf][r + g][kb + tg * 2 + 8];
                af[mi][3] = *(const unsigned*)&As[buf][r + g + 8][kb + tg * 2 + 8];
            }
#pragma unroll
            for (int ni = 0; ni < 4; ni++) {
                int r = wn + ni * 8;
                bfv[ni][0] = *(const unsigned*)&Bs[buf][r + g][kb + tg * 2];
                bfv[ni][1] = *(const unsigned*)&Bs[buf][r + g][kb + tg * 2 + 8];
            }
#pragma unroll
            for (int mi = 0; mi < 4; mi++)
#pragma unroll
                for (int ni = 0; ni < 4; ni++)
                    mma16816(acc[mi][ni], af[mi], bfv[ni]);
        }
        __syncthreads();
    }
    // epilogue: smem transpose in 32-col chunks -> coalesced NCHW writes
    float (*sbuf)[33] = (float(*)[33])sm_raw;
    int cc = tid >> 3, seg = tid & 7;
#pragma unroll
    for (int nc = 0; nc < 4; nc++) {
        if ((wid >> 1) == nc) {
#pragma unroll
            for (int mi = 0; mi < 4; mi++)
#pragma unroll
                for (int ni = 0; ni < 4; ni++)
#pragma unroll
                    for (int rr = 0; rr < 2; rr++)
#pragma unroll
                        for (int j = 0; j < 2; j++)
                            sbuf[wm + mi * 16 + g + rr * 8][ni * 8 + tg * 2 + j] =
                                acc[mi][ni][rr * 2 + j];
        }
        __syncthreads();
        int col = n0 + nc * 32 + cc;
        float gb = gamma[col], bb = bias2[col];
        size_t colbase = ((size_t)(m0 >> 10) * DIM + col) * NPIX + (m0 & 1023);
#pragma unroll
        for (int q = 0; q < 4; q++) {
            int r = q * 32 + seg * 4;
            float4 xv = *(const float4*)&xin[colbase + r];
            float4 o;
            o.x = xv.x + gb * (sbuf[r + 0][cc] + bb);
            o.y = xv.y + gb * (sbuf[r + 1][cc] + bb);
            o.z = xv.z + gb * (sbuf[r + 2][cc] + bb);
            o.w = xv.w + gb * (sbuf[r + 3][cc] + bb);
            *(float4*)&out[colbase + r] = o;
        }
        __syncthreads();
    }
}

// ---------------- host launcher ----------------
extern "C" void kernel_launch(void* const* d_in, const int* in_sizes, int n_in,
                              void* d_out, int out_size)
{
    const float* x      = (const float*)d_in[0];
    const float* pe_w1  = (const float*)d_in[1];
    const float* pe_bng = (const float*)d_in[2];
    const float* pe_bnb = (const float*)d_in[3];
    const float* pe_bnm = (const float*)d_in[4];
    const float* pe_bnv = (const float*)d_in[5];
    const float* pe_w2  = (const float*)d_in[6];
    const float* pe_b2  = (const float*)d_in[7];
    const float* kg_w1  = (const float*)d_in[8];
    const float* kg_bng = (const float*)d_in[9];
    const float* kg_bnb = (const float*)d_in[10];
    const float* kg_bnm = (const float*)d_in[11];
    const float* kg_bnv = (const float*)d_in[12];
    const float* kg_w2  = (const float*)d_in[13];
    const float* kg_b2  = (const float*)d_in[14];
    const float* bias   = (const float*)d_in[15];
    const float* ln_w   = (const float*)d_in[16];
    const float* ln_b   = (const float*)d_in[17];
    const float* pw1_w  = (const float*)d_in[18];
    const float* pw1_b  = (const float*)d_in[19];
    const float* pw2_w  = (const float*)d_in[20];
    const float* pw2_b  = (const float*)d_in[21];
    const float* gamma  = (const float*)d_in[22];
    float* outp = (float*)d_out;

    bf16 *pxtok, *pxtok2, *phtok, *pkwtok, *pybf, *pmid, *pw1bf, *pw2bf;
    bf16 *pw1pe, *pw1kg, *pw2pe, *pw2kg;
    float *pxp, *py, *pHw, *pWw;
    cudaGetSymbolAddress((void**)&pxtok,  g_xtok);
    cudaGetSymbolAddress((void**)&pxtok2, g_xtok2);
    cudaGetSymbolAddress((void**)&phtok,  g_htok);
    cudaGetSymbolAddress((void**)&pkwtok, g_kwtok);
    cudaGetSymbolAddress((void**)&pxp, g_xp);
    cudaGetSymbolAddress((void**)&py,  g_y);
    cudaGetSymbolAddress((void**)&pHw, g_Hw);
    cudaGetSymbolAddress((void**)&pWw, g_Ww);
    cudaGetSymbolAddress((void**)&pybf,  g_ybf);
    cudaGetSymbolAddress((void**)&pmid,  g_mid);
    cudaGetSymbolAddress((void**)&pw1bf, g_w1bf);
    cudaGetSymbolAddress((void**)&pw2bf, g_w2bf);
    cudaGetSymbolAddress((void**)&pw1pe, g_w1pe);
    cudaGetSymbolAddress((void**)&pw1kg, g_w1kg);
    cudaGetSymbolAddress((void**)&pw2pe, g_w2pe);
    cudaGetSymbolAddress((void**)&pw2kg, g_w2kg);

    cvt_weights<<<(FDIM * DIM + 255) / 256, 256>>>(pw1_w, pw2_w, pw1bf, pw2bf);
    cvt_convw<<<(MIDC * DIM * 9 + 255) / 256, 256>>>(pe_w1, kg_w1, pe_w2, kg_w2,
                                                     pw1pe, pw1kg, pw2pe, pw2kg);
    nchw2tok<<<dim3(8, 4, BATCH), 256>>>(x, pxtok);

    conv1_tok<<<NTOK / 64, 256>>>(pxtok, pw1pe, pe_bng, pe_bnb, pe_bnm, pe_bnv, phtok);
    conv2_tok<<<dim3(8, NTOK / 128), 256>>>(phtok, pw2pe, pe_b2, pxtok, pxtok2);
    conv1_tok<<<NTOK / 64, 256>>>(pxtok2, pw1kg, kg_bng, kg_bnb, kg_bnm, kg_bnv, phtok);
    conv2_tok<<<dim3(8, NTOK / 128), 256>>>(phtok, pw2kg, kg_b2, nullptr, pkwtok);

    tok2nchw<<<dim3(8, 4, BATCH), 256>>>(pxtok2, pxp);

    reduce_tok<<<dim3(32, BATCH), 512>>>(pkwtok, pHw, pWw);

    circ_kernel<<<(BATCH * DIM) / 4, 256>>>(pxp, pHw, pWw, bias, py);

    ln2_kernel<<<dim3(8, BATCH), 256>>>(py, ln_w, ln_b, pybf);

    gemm1_gelu<<<dim3(FDIM / BN, NTOK / BM), 256>>>(pybf, pw1bf, pw1_b, pmid);
    gemm2_res<<<dim3(DIM / BN, NTOK / BM), 256>>>(pmid, pw2bf, pw2_b, gamma, x, outp);
}

// round 5
// speedup vs baseline: 2.7250x; 1.0197x over previous
#include <cuda_runtime.h>
#include <cuda_bf16.h>
#include <math.h>

#define BATCH 16
#define DIM 512
#define MIDC 32
#define NPIX 1024
#define NTOK 16384
#define FDIM 2048

typedef __nv_bfloat16 bf16;

// ---------------- scratch (static device memory) ----------------
__device__ bf16 g_xtok [NTOK * DIM];
__device__ bf16 g_xtok2[NTOK * DIM];
__device__ bf16 g_htok [NTOK * MIDC];
__device__ bf16 g_kwtok[NTOK * DIM];
__device__ float g_xp[BATCH * DIM * NPIX];
__device__ float g_y [BATCH * DIM * NPIX];
__device__ float g_Hw[BATCH * 256 * 32];
__device__ float g_Ww[BATCH * 256 * 32];
__device__ bf16 g_ybf[NTOK * DIM];
__device__ bf16 g_mid[NTOK * FDIM];
__device__ bf16 g_w1bf[FDIM * DIM];
__device__ bf16 g_w2bf[DIM * FDIM];
__device__ bf16 g_w1pe[9 * MIDC * DIM];
__device__ bf16 g_w1kg[9 * MIDC * DIM];
__device__ bf16 g_w2pe[9 * DIM * MIDC];
__device__ bf16 g_w2kg[9 * DIM * MIDC];

// ---------------- cp.async / ldmatrix helpers ----------------
__device__ __forceinline__ void cp16(void* s, const void* g) {
    unsigned sa = (unsigned)__cvta_generic_to_shared(s);
    asm volatile("cp.async.cg.shared.global [%0], [%1], 16;\n" :: "r"(sa), "l"(g));
}
__device__ __forceinline__ void cp16p(void* s, const void* g, bool pred) {
    unsigned sa = (unsigned)__cvta_generic_to_shared(s);
    int sz = pred ? 16 : 0;
    asm volatile("cp.async.cg.shared.global [%0], [%1], 16, %2;\n" :: "r"(sa), "l"(g), "r"(sz));
}
#define CP_COMMIT() asm volatile("cp.async.commit_group;\n")
#define CP_WAIT(n)  asm volatile("cp.async.wait_group %0;\n" :: "n"(n))

__device__ __forceinline__ void ldmx4(unsigned* r, const void* p) {
    unsigned a = (unsigned)__cvta_generic_to_shared(p);
    asm volatile("ldmatrix.sync.aligned.m8n8.x4.shared.b16 {%0,%1,%2,%3}, [%4];\n"
                 : "=r"(r[0]), "=r"(r[1]), "=r"(r[2]), "=r"(r[3]) : "r"(a));
}

// ---------------- weight conversions ----------------
__global__ void cvt_weights(const float* __restrict__ w1, const float* __restrict__ w2,
                            bf16* __restrict__ o1, bf16* __restrict__ o2)
{
    int i = blockIdx.x * blockDim.x + threadIdx.x;
    if (i < FDIM * DIM) {
        o1[i] = __float2bfloat16(w1[i]);
        o2[i] = __float2bfloat16(w2[i]);
    }
}

__global__ void cvt_convw(const float* __restrict__ pw1, const float* __restrict__ kw1,
                          const float* __restrict__ pw2, const float* __restrict__ kw2,
                          bf16* __restrict__ o1p, bf16* __restrict__ o1k,
                          bf16* __restrict__ o2p, bf16* __restrict__ o2k)
{
    int i = blockIdx.x * blockDim.x + threadIdx.x;
    if (i >= MIDC * DIM * 9) return;
    int off = i % 9;
    int ic = (i / 9) % DIM, oc = i / (9 * DIM);
    o1p[(off * MIDC + oc) * DIM + ic] = __float2bfloat16(pw1[i]);
    o1k[(off * MIDC + oc) * DIM + ic] = __float2bfloat16(kw1[i]);
    int ic2 = (i / 9) % MIDC, oc2 = i / (9 * MIDC);
    o2p[(off * DIM + oc2) * MIDC + ic2] = __float2bfloat16(pw2[i]);
    o2k[(off * DIM + oc2) * MIDC + ic2] = __float2bfloat16(kw2[i]);
}

// ---------------- NCHW fp32 -> token bf16 transpose ----------------
__global__ __launch_bounds__(256) void nchw2tok(const float* __restrict__ X, bf16* __restrict__ T)
{
    __shared__ bf16 sm[128][136];
    int hw0 = blockIdx.x * 128, c0 = blockIdx.y * 128, b = blockIdx.z;
    int tid = threadIdx.x;
    const float* xp = X + ((size_t)b * DIM + c0) * NPIX + hw0;
#pragma unroll
    for (int i = 0; i < 16; i++) {
        int idx = tid + i * 256;
        int rc = idx >> 5, u = idx & 31;
        float4 v = *(const float4*)&xp[(size_t)rc * NPIX + u * 4];
        union { uint2 q; bf16 h[4]; } pk;
        pk.h[0] = __float2bfloat16(v.x); pk.h[1] = __float2bfloat16(v.y);
        pk.h[2] = __float2bfloat16(v.z); pk.h[3] = __float2bfloat16(v.w);
        *(uint2*)&sm[rc][u * 4] = pk.q;
    }
    __syncthreads();
    bf16* tp = T + ((size_t)(b * NPIX + hw0)) * DIM + c0;
#pragma unroll
    for (int i = 0; i < 8; i++) {
        int idx = tid + i * 256;
        int rt = idx >> 4, uu = idx & 15;
        union { uint4 q; bf16 h[8]; } pk;
#pragma unroll
        for (int j = 0; j < 8; j++) pk.h[j] = sm[uu * 8 + j][rt];
        *(uint4*)&tp[(size_t)rt * DIM + uu * 8] = pk.q;
    }
}

// ---------------- token bf16 -> NCHW fp32 transpose ----------------
__global__ __launch_bounds__(256) void tok2nchw(const bf16* __restrict__ T, float* __restrict__ X)
{
    __shared__ bf16 sm[128][136];
    int hw0 = blockIdx.x * 128, c0 = blockIdx.y * 128, b = blockIdx.z;
    int tid = threadIdx.x;
    const bf16* tp = T + ((size_t)(b * NPIX + hw0)) * DIM + c0;
#pragma unroll
    for (int i = 0; i < 8; i++) {
        int idx = tid + i * 256;
        int rt = idx >> 4, uu = idx & 15;
        *(uint4*)&sm[rt][uu * 8] = *(const uint4*)&tp[(size_t)rt * DIM + uu * 8];
    }
    __syncthreads();
    float* xp = X + ((size_t)b * DIM + c0) * NPIX + hw0;
#pragma unroll
    for (int i = 0; i < 16; i++) {
        int idx = tid + i * 256;
        int rc = idx >> 5, u = idx & 31;
        float4 v;
        v.x = __bfloat162float(sm[u * 4 + 0][rc]);
        v.y = __bfloat162float(sm[u * 4 + 1][rc]);
        v.z = __bfloat162float(sm[u * 4 + 2][rc]);
        v.w = __bfloat162float(sm[u * 4 + 3][rc]);
        *(float4*)&xp[(size_t)rc * NPIX + u * 4] = v;
    }
}

// ---------------- MMA helper ----------------
__device__ __forceinline__ void mma16816(float* d, const unsigned* a, const unsigned* b) {
    asm volatile(
        "mma.sync.aligned.m16n8k16.row.col.f32.bf16.bf16.f32 "
        "{%0,%1,%2,%3}, {%4,%5,%6,%7}, {%8,%9}, {%0,%1,%2,%3};\n"
        : "+f"(d[0]), "+f"(d[1]), "+f"(d[2]), "+f"(d[3])
        : "r"(a[0]), "r"(a[1]), "r"(a[2]), "r"(a[3]), "r"(b[0]), "r"(b[1]));
}

// ---------------- conv1 implicit GEMM (3-stage cp.async + ldmatrix) ---------
// M tile 64, N=32, K = 9 offsets x 512 (72 k-tiles of 64)
#define C1S 72
#define C1KT 72
__global__ __launch_bounds__(256) void conv1_tok(
    const bf16* __restrict__ X, const bf16* __restrict__ W,
    const float* __restrict__ bng, const float* __restrict__ bnb,
    const float* __restrict__ bnm, const float* __restrict__ bnv,
    bf16* __restrict__ O)
{
    __shared__ __align__(16) bf16 As[3][64][C1S];
    __shared__ __align__(16) bf16 Bs[3][32][C1S];
    __shared__ __align__(16) bf16 Cs[64][48];
    __shared__ float sS[32], sT[32];
    int m0 = blockIdx.x * 64;
    int tid = threadIdx.x;
    if (tid < 32) {
        float inv = rsqrtf(bnv[tid] + 1e-5f);
        float s = bng[tid] * inv;
        sS[tid] = s;
        sT[tid] = bnb[tid] - bnm[tid] * s;
    }
    int ar = tid >> 2, aq = (tid & 3) * 16;
    int t = m0 + ar;
    int th = (t >> 5) & 31, tw = t & 31;
    int br = tid >> 3, bq = (tid & 7) * 8;
    int wid = tid >> 5, lane = tid & 31;
    int wm = (wid & 3) * 16, wn = (wid >> 2) * 16;
    int g = lane >> 2, tg = lane & 3;
    int lrow = (lane & 7) + ((lane >> 3) & 1) * 8;  // ldmatrix row within 16
    int lcol = ((lane >> 4) & 1) * 8;               // ldmatrix col half

    float acc[2][4];
#pragma unroll
    for (int i = 0; i < 2; i++)
#pragma unroll
        for (int j = 0; j < 4; j++) acc[i][j] = 0.f;

    auto load_tile = [&](int kt, int buf) {
        int off = kt >> 3, k0 = (kt & 7) * 64;
        int dy = off / 3 - 1, dx = off % 3 - 1;
        bool valid = ((unsigned)(th + dy) < 32u) && ((unsigned)(tw + dx) < 32u);
        const bf16* srcA = X + ((long)(t + dy * 32 + dx)) * DIM + k0 + aq;
        cp16p(&As[buf][ar][aq], srcA, valid);
        cp16p(&As[buf][ar][aq + 8], srcA + 8, valid);
        const bf16* srcB = W + (size_t)(off * MIDC + br) * DIM + k0 + bq;
        cp16(&Bs[buf][br][bq], srcB);
    };

    load_tile(0, 0);
    CP_COMMIT();
    load_tile(1, 1);
    CP_COMMIT();
    for (int kt = 0; kt < C1KT; kt++) {
        int buf = kt % 3;
        if (kt + 1 < C1KT) { CP_WAIT(1); } else { CP_WAIT(0); }
        __syncthreads();
        if (kt + 2 < C1KT) {
            load_tile(kt + 2, (kt + 2) % 3);
            CP_COMMIT();
        }
#pragma unroll
        for (int kc = 0; kc < 4; kc++) {
            int kb = kc * 16;
            unsigned a[4], bb[4];
            ldmx4(a,  &As[buf][wm + lrow][kb + lcol]);
            ldmx4(bb, &Bs[buf][wn + lrow][kb + lcol]);
            unsigned b0[2] = { bb[0], bb[2] };
            unsigned b1[2] = { bb[1], bb[3] };
            mma16816(acc[0], a, b0);
            mma16816(acc[1], a, b1);
        }
    }
    __syncthreads();
#pragma unroll
    for (int ni = 0; ni < 2; ni++)
#pragma unroll
        for (int rr = 0; rr < 2; rr++)
#pragma unroll
            for (int j = 0; j < 2; j++) {
                int col = wn + ni * 8 + tg * 2 + j;
                int row = wm + g + rr * 8;
                float v = acc[ni][rr * 2 + j] * sS[col] + sT[col];
                Cs[row][col] = __float2bfloat16(fmaxf(v, 0.f));
            }
    __syncthreads();
    int orow = tid >> 2, oq = (tid & 3) * 8;
    *(uint4*)&O[(size_t)(m0 + orow) * MIDC + oq] = *(uint4*)&Cs[orow][oq];
}

// ---------------- conv2 implicit GEMM (2-stage cp.async + ldmatrix) ---------
// M tile 128, N tile 64, K = 9 x 32
__global__ __launch_bounds__(256) void conv2_tok(
    const bf16* __restrict__ Hx, const bf16* __restrict__ W,
    const float* __restrict__ b2, const bf16* __restrict__ res,
    bf16* __restrict__ O)
{
    __shared__ __align__(16) bf16 As[2][128][40];
    __shared__ __align__(16) bf16 Bs[2][64][40];
    int n0 = blockIdx.x * 64, m0 = blockIdx.y * 128;
    int tid = threadIdx.x;
    int ar = tid >> 1, aq = (tid & 1) * 16;
    int t = m0 + ar;
    int th = (t >> 5) & 31, tw = t & 31;
    int br = tid >> 2, bq = (tid & 3) * 8;
    int wid = tid >> 5, lane = tid & 31;
    int wm = (wid & 3) * 32, wn = (wid >> 2) * 32;
    int g = lane >> 2, tg = lane & 3;
    int lrow = (lane & 7) + ((lane >> 3) & 1) * 8;
    int lcol = ((lane >> 4) & 1) * 8;

    float acc[2][4][4];
#pragma unroll
    for (int i = 0; i < 2; i++)
#pragma unroll
        for (int j = 0; j < 4; j++)
#pragma unroll
            for (int k = 0; k < 4; k++) acc[i][j][k] = 0.f;

    auto load_tile = [&](int off, int buf) {
        int dy = off / 3 - 1, dx = off % 3 - 1;
        bool valid = ((unsigned)(th + dy) < 32u) && ((unsigned)(tw + dx) < 32u);
        const bf16* srcA = Hx + ((long)(t + dy * 32 + dx)) * MIDC + aq;
        cp16p(&As[buf][ar][aq], srcA, valid);
        cp16p(&As[buf][ar][aq + 8], srcA + 8, valid);
        cp16(&Bs[buf][br][bq], &W[(size_t)(off * DIM + n0 + br) * MIDC + bq]);
    };

    load_tile(0, 0);
    CP_COMMIT();
    for (int off = 0; off < 9; off++) {
        int buf = off & 1;
        if (off < 8) {
            load_tile(off + 1, buf ^ 1);
            CP_COMMIT();
            CP_WAIT(1);
        } else {
            CP_WAIT(0);
        }
        __syncthreads();
#pragma unroll
        for (int kc = 0; kc < 2; kc++) {
            int kb = kc * 16;
            unsigned a[2][4], bb[2][4];
#pragma unroll
            for (int mi = 0; mi < 2; mi++)
                ldmx4(a[mi], &As[buf][wm + mi * 16 + lrow][kb + lcol]);
#pragma unroll
            for (int nh = 0; nh < 2; nh++)
                ldmx4(bb[nh], &Bs[buf][wn + nh * 16 + lrow][kb + lcol]);
#pragma unroll
            for (int mi = 0; mi < 2; mi++)
#pragma unroll
                for (int ni = 0; ni < 4; ni++) {
                    unsigned bfr[2] = { bb[ni >> 1][ni & 1], bb[ni >> 1][(ni & 1) + 2] };
                    mma16816(acc[mi][ni], a[mi], bfr);
                }
        }
        __syncthreads();
    }
    float bv0[4], bv1[4];
#pragma unroll
    for (int ni = 0; ni < 4; ni++) {
        int col = n0 + wn + ni * 8 + tg * 2;
        bv0[ni] = b2[col];
        bv1[ni] = b2[col + 1];
    }
#pragma unroll
    for (int mi = 0; mi < 2; mi++)
#pragma unroll
        for (int ni = 0; ni < 4; ni++)
#pragma unroll
            for (int rr = 0; rr < 2; rr++) {
                int row = m0 + wm + mi * 16 + g + rr * 8;
                size_t ad = (size_t)row * DIM + n0 + wn + ni * 8 + tg * 2;
                float v0 = acc[mi][ni][rr * 2 + 0] + bv0[ni];
                float v1 = acc[mi][ni][rr * 2 + 1] + bv1[ni];
                if (res) {
                    __nv_bfloat162 rv = *(const __nv_bfloat162*)&res[ad];
                    v0 += __bfloat162float(rv.x);
                    v1 += __bfloat162float(rv.y);
                }
                __nv_bfloat162 p;
                p.x = __float2bfloat16(v0);
                p.y = __float2bfloat16(v1);
                *(__nv_bfloat162*)&O[ad] = p;
            }
}

// ---------------- fused mean reductions (H and W halves) --------------------
__global__ __launch_bounds__(512) void reduce_tok(const bf16* __restrict__ T,
                                                  float* __restrict__ Hw,
                                                  float* __restrict__ Ww)
{
    int q = blockIdx.x, b = blockIdx.y;
    int tid = threadIdx.x;
    if (tid < 256) {
        int c = tid;
        const bf16* p = T + (size_t)(b * NPIX + q * 32) * DIM + c;
        float s = 0.f;
#pragma unroll
        for (int w = 0; w < 32; w++) s += __bfloat162float(p[(size_t)w * DIM]);
        Hw[((size_t)b * 256 + c) * 32 + q] = s * (1.f / 32.f);
    } else {
        int c = tid - 256;
        const bf16* p = T + (size_t)(b * NPIX + q) * DIM + 256 + c;
        float s = 0.f;
#pragma unroll
        for (int h = 0; h < 32; h++) s += __bfloat162float(p[(size_t)h * 32 * DIM]);
        Ww[((size_t)b * 256 + c) * 32 + q] = s * (1.f / 32.f);
    }
}

// ---------------- circular 32x32 matmuls + bias, writes y (NCHW fp32) -------
__global__ __launch_bounds__(256) void circ_kernel(
    const float* __restrict__ x, const float* __restrict__ Hw,
    const float* __restrict__ Ww, const float* __restrict__ bias,
    float* __restrict__ y)
{
    __shared__ float xs[4][32][36];
    __shared__ float kv[4][32];
    int p0 = blockIdx.x * 4;
    int tid = threadIdx.x;
    int lp = tid >> 6;
    int lt = tid & 63;
    int plane = p0 + lp;
    int b = plane >> 9, c = plane & 511;
    const float* xp = x + (size_t)plane * NPIX;
    for (int idx = lt; idx < NPIX; idx += 64) {
        int r = idx >> 5, cc = idx & 31;
        xs[lp][r][cc] = xp[idx];
    }
    if (lt < 32)
        kv[lp][lt] = (c < 256) ? Hw[((size_t)b * 256 + c) * 32 + lt]
                               : Ww[((size_t)b * 256 + (c - 256)) * 32 + lt];
    __syncthreads();

    int t_r = (lt >> 3) * 4;
    int t_c = (lt & 7) * 4;
    float acc[4][4];
#pragma unroll
    for (int r = 0; r < 4; r++)
#pragma unroll
        for (int cc = 0; cc < 4; cc++) acc[r][cc] = 0.f;
    float bv = bias[c];

    if (c < 256) {
        float kr[32];
#pragma unroll
        for (int u = 0; u < 32; u++) kr[u] = kv[lp][(u - t_r) & 31];
#pragma unroll
        for (int j = 0; j < 32; j++) {
            float4 xv = *(const float4*)&xs[lp][j][t_c];
#pragma unroll
            for (int ri = 0; ri < 4; ri++) {
                float kk = kr[(j - ri) & 31];
                acc[ri][0] += kk * xv.x;
                acc[ri][1] += kk * xv.y;
                acc[ri][2] += kk * xv.z;
                acc[ri][3] += kk * xv.w;
            }
        }
    } else {
        float kr[32];
#pragma unroll
        for (int u = 0; u < 32; u++) kr[u] = kv[lp][(u - t_c) & 31];
#pragma unroll
        for (int j = 0; j < 32; j++) {
            float xv[4];
#pragma unroll
            for (int ri = 0; ri < 4; ri++) xv[ri] = xs[lp][t_r + ri][j];
#pragma unroll
            for (int ci = 0; ci < 4; ci++) {
                float kk = kr[(j - ci) & 31];
#pragma unroll
                for (int ri = 0; ri < 4; ri++) acc[ri][ci] += kk * xv[ri];
            }
        }
    }
    float* yp = y + (size_t)plane * NPIX;
#pragma unroll
    for (int ri = 0; ri < 4; ri++) {
        float4 o;
        o.x = acc[ri][0] + bv; o.y = acc[ri][1] + bv;
        o.z = acc[ri][2] + bv; o.w = acc[ri][3] + bv;
        *(float4*)&yp[(t_r + ri) * 32 + t_c] = o;
    }
}

// ---------------- coalesced two-pass LayerNorm: NCHW fp32 -> token bf16 -----
__global__ __launch_bounds__(256) void ln2_kernel(
    const float* __restrict__ Y, const float* __restrict__ lnw,
    const float* __restrict__ lnb, bf16* __restrict__ O)
{
    __shared__ float mus[128], rss[128];
    __shared__ float ps[256], ps2[256];
    __shared__ float wgt[512], bta[512];
    __shared__ __align__(16) bf16 sm[128][136];
    int chunk = blockIdx.x, b = blockIdx.y;
    int hw0 = chunk * 128;
    int tid = threadIdx.x;
    for (int i = tid; i < 512; i += 256) { wgt[i] = lnw[i]; bta[i] = lnb[i]; }
    int j = tid & 127, half = tid >> 7;
    const float* yb = Y + (size_t)b * DIM * NPIX + hw0 + j;
    float s = 0.f, s2 = 0.f;
    for (int c = half * 256; c < half * 256 + 256; c++) {
        float v = yb[(size_t)c * NPIX];
        s += v; s2 += v * v;
    }
    ps[tid] = s; ps2[tid] = s2;
    __syncthreads();
    if (tid < 128) {
        float S = ps[tid] + ps[tid + 128];
        float S2 = ps2[tid] + ps2[tid + 128];
        float mu = S * (1.f / 512.f);
        float var = S2 * (1.f / 512.f) - mu * mu;
        mus[tid] = mu;
        rss[tid] = rsqrtf(var + 1e-6f);
    }
    __syncthreads();
    float mu = mus[j], rstd = rss[j];
    size_t t0 = (size_t)b * NPIX + hw0;
#pragma unroll
    for (int r = 0; r < 4; r++) {
        int cbase = r * 128 + half * 64;
#pragma unroll 4
        for (int i = 0; i < 64; i++) {
            int c = cbase + i;
            float v = yb[(size_t)c * NPIX];
            float o = (v - mu) * rstd * wgt[c] + bta[c];
            sm[j][half * 64 + i] = __float2bfloat16(o);
        }
        __syncthreads();
        int rt = tid >> 1, u = tid & 1;
        const uint4* src = (const uint4*)&sm[rt][u * 64];
        uint4* dst = (uint4*)&O[(t0 + rt) * DIM + r * 128 + u * 64];
#pragma unroll
        for (int q = 0; q < 8; q++) dst[q] = src[q];
        __syncthreads();
    }
}

__device__ __forceinline__ float gelu_exact(float x) {
    return 0.5f * x * (1.f + erff(x * 0.70710678118654752f));
}

#define BM 128
#define BN 128
#define SSTR 40

// GEMM1: C[16384,2048] = gelu(A[16384,512] * W1[2048,512]^T + b)  (3-stage)
__global__ __launch_bounds__(256) void gemm1_gelu(
    const bf16* __restrict__ A, const bf16* __restrict__ Bw,
    const float* __restrict__ bias, bf16* __restrict__ C)
{
    const int K = DIM, KT = K / 32;
    __shared__ __align__(16) bf16 As[3][BM][SSTR];
    __shared__ __align__(16) bf16 Bs[3][BN][SSTR];
    int m0 = blockIdx.y * BM, n0 = blockIdx.x * BN;
    int tid = threadIdx.x;
    int wid = tid >> 5, lane = tid & 31;
    int wm = (wid & 1) * 64, wn = (wid >> 1) * 32;
    int g = lane >> 2, tg = lane & 3;
    int lrow = (lane & 7) + ((lane >> 3) & 1) * 8;
    int lcol = ((lane >> 4) & 1) * 8;
    float acc[4][4][4];
#pragma unroll
    for (int i = 0; i < 4; i++)
#pragma unroll
        for (int j = 0; j < 4; j++)
#pragma unroll
            for (int k = 0; k < 4; k++) acc[i][j][k] = 0.f;

    int lr = tid >> 1, lc = (tid & 1) * 16;
    const bf16* apb = &A[(size_t)(m0 + lr) * K + lc];
    const bf16* bpb = &Bw[(size_t)(n0 + lr) * K + lc];

    auto load_tile = [&](int kt, int buf) {
        cp16(&As[buf][lr][lc],     apb + kt * 32);
        cp16(&As[buf][lr][lc + 8], apb + kt * 32 + 8);
        cp16(&Bs[buf][lr][lc],     bpb + kt * 32);
        cp16(&Bs[buf][lr][lc + 8], bpb + kt * 32 + 8);
    };

    load_tile(0, 0);
    CP_COMMIT();
    load_tile(1, 1);
    CP_COMMIT();
    for (int kt = 0; kt < KT; kt++) {
        int buf = kt % 3;
        if (kt + 1 < KT) { CP_WAIT(1); } else { CP_WAIT(0); }
        __syncthreads();
        if (kt + 2 < KT) {
            load_tile(kt + 2, (kt + 2) % 3);
            CP_COMMIT();
        }
#pragma unroll
        for (int ks = 0; ks < 2; ks++) {
            int kb = ks * 16;
            unsigned af[4][4], bb[2][4];
#pragma unroll
            for (int mi = 0; mi < 4; mi++)
                ldmx4(af[mi], &As[buf][wm + mi * 16 + lrow][kb + lcol]);
#pragma unroll
            for (int nh = 0; nh < 2; nh++)
                ldmx4(bb[nh], &Bs[buf][wn + nh * 16 + lrow][kb + lcol]);
#pragma unroll
            for (int mi = 0; mi < 4; mi++)
#pragma unroll
                for (int ni = 0; ni < 4; ni++) {
                    unsigned bfr[2] = { bb[ni >> 1][ni & 1], bb[ni >> 1][(ni & 1) + 2] };
                    mma16816(acc[mi][ni], af[mi], bfr);
                }
        }
    }
#pragma unroll
    for (int mi = 0; mi < 4; mi++)
#pragma unroll
        for (int ni = 0; ni < 4; ni++) {
            int col = n0 + wn + ni * 8 + tg * 2;
            float b0 = bias[col], b1 = bias[col + 1];
            int row0 = m0 + wm + mi * 16 + g;
#pragma unroll
            for (int rr = 0; rr < 2; rr++) {
                int r = row0 + rr * 8;
                float v0 = gelu_exact(acc[mi][ni][rr * 2 + 0] + b0);
                float v1 = gelu_exact(acc[mi][ni][rr * 2 + 1] + b1);
                __nv_bfloat162 p;
                p.x = __float2bfloat16(v0);
                p.y = __float2bfloat16(v1);
                *(__nv_bfloat162*)&C[(size_t)r * FDIM + col] = p;
            }
        }
}

// GEMM2: out = x_in + gamma*(A*W2^T + b), 3-stage + coalesced NCHW epilogue
__global__ __launch_bounds__(256) void gemm2_res(
    const bf16* __restrict__ A, const bf16* __restrict__ Bw,
    const float* __restrict__ bias2, const float* __restrict__ gamma,
    const float* __restrict__ xin, float* __restrict__ out)
{
    const int K = FDIM, KT = K / 32;
    __shared__ __align__(16) char sm_raw[3 * BM * SSTR * 2 + 3 * BN * SSTR * 2];
    bf16 (*As)[BM][SSTR] = (bf16(*)[BM][SSTR])sm_raw;
    bf16 (*Bs)[BN][SSTR] = (bf16(*)[BN][SSTR])(sm_raw + 3 * BM * SSTR * 2);
    int m0 = blockIdx.y * BM, n0 = blockIdx.x * BN;
    int tid = threadIdx.x;
    int wid = tid >> 5, lane = tid & 31;
    int wm = (wid & 1) * 64, wn = (wid >> 1) * 32;
    int g = lane >> 2, tg = lane & 3;
    int lrow = (lane & 7) + ((lane >> 3) & 1) * 8;
    int lcol = ((lane >> 4) & 1) * 8;
    float acc[4][4][4];
#pragma unroll
    for (int i = 0; i < 4; i++)
#pragma unroll
        for (int j = 0; j < 4; j++)
#pragma unroll
            for (int k = 0; k < 4; k++) acc[i][j][k] = 0.f;

    int lr = tid >> 1, lc = (tid & 1) * 16;
    const bf16* apb = &A[(size_t)(m0 + lr) * K + lc];
    const bf16* bpb = &Bw[(size_t)(n0 + lr) * K + lc];

    auto load_tile = [&](int kt, int buf) {
        cp16(&As[buf][lr][lc],     apb + kt * 32);
        cp16(&As[buf][lr][lc + 8], apb + kt * 32 + 8);
        cp16(&Bs[buf][lr][lc],     bpb + kt * 32);
        cp16(&Bs[buf][lr][lc + 8], bpb + kt * 32 + 8);
    };

    load_tile(0, 0);
    CP_COMMIT();
    load_tile(1, 1);
    CP_COMMIT();
    for (int kt = 0; kt < KT; kt++) {
        int buf = kt % 3;
        if (kt + 1 < KT) { CP_WAIT(1); } else { CP_WAIT(0); }
        __syncthreads();
        if (kt + 2 < KT) {
            load_tile(kt + 2, (kt + 2) % 3);
            CP_COMMIT();
        }
#pragma unroll
        for (int ks = 0; ks < 2; ks++) {
            int kb = ks * 16;
            unsigned af[4][4], bb[2][4];
#pragma unroll
            for (int mi = 0; mi < 4; mi++)
                ldmx4(af[mi], &As[buf][wm + mi * 16 + lrow][kb + lcol]);
#pragma unroll
            for (int nh = 0; nh < 2; nh++)
                ldmx4(bb[nh], &Bs[buf][wn + nh * 16 + lrow][kb + lcol]);
#pragma unroll
            for (int mi = 0; mi < 4; mi++)
#pragma unroll
                for (int ni = 0; ni < 4; ni++) {
                    unsigned bfr[2] = { bb[ni >> 1][ni & 1], bb[ni >> 1][(ni & 1) + 2] };
                    mma16816(acc[mi][ni], af[mi], bfr);
                }
        }
    }
    __syncthreads();
    // epilogue: smem transpose in 32-col chunks -> coalesced NCHW writes
    float (*sbuf)[33] = (float(*)[33])sm_raw;
    int cc = tid >> 3, seg = tid & 7;
#pragma unroll
    for (int nc = 0; nc < 4; nc++) {
        if ((wid >> 1) == nc) {
#pragma unroll
            for (int mi = 0; mi < 4; mi++)
#pragma unroll
                for (int ni = 0; ni < 4; ni++)
#pragma unroll
                    for (int rr = 0; rr < 2; rr++)
#pragma unroll
                        for (int j = 0; j < 2; j++)
                            sbuf[wm + mi * 16 + g + rr * 8][ni * 8 + tg * 2 + j] =
                                acc[mi][ni][rr * 2 + j];
        }
        __syncthreads();
        int col = n0 + nc * 32 + cc;
        float gb = gamma[col], bb2 = bias2[col];
        size_t colbase = ((size_t)(m0 >> 10) * DIM + col) * NPIX + (m0 & 1023);
#pragma unroll
        for (int q = 0; q < 4; q++) {
            int r = q * 32 + seg * 4;
            float4 xv = *(const float4*)&xin[colbase + r];
            float4 o;
            o.x = xv.x + gb * (sbuf[r + 0][cc] + bb2);
            o.y = xv.y + gb * (sbuf[r + 1][cc] + bb2);
            o.z = xv.z + gb * (sbuf[r + 2][cc] + bb2);
            o.w = xv.w + gb * (sbuf[r + 3][cc] + bb2);
            *(float4*)&out[colbase + r] = o;
        }
        __syncthreads();
    }
}

// ---------------- host launcher ----------------
extern "C" void kernel_launch(void* const* d_in, const int* in_sizes, int n_in,
                              void* d_out, int out_size)
{
    const float* x      = (const float*)d_in[0];
    const float* pe_w1  = (const float*)d_in[1];
    const float* pe_bng = (const float*)d_in[2];
    const float* pe_bnb = (const float*)d_in[3];
    const float* pe_bnm = (const float*)d_in[4];
    const float* pe_bnv = (const float*)d_in[5];
    const float* pe_w2  = (const float*)d_in[6];
    const float* pe_b2  = (const float*)d_in[7];
    const float* kg_w1  = (const float*)d_in[8];
    const float* kg_bng = (const float*)d_in[9];
    const float* kg_bnb = (const float*)d_in[10];
    const float* kg_bnm = (const float*)d_in[11];
    const float* kg_bnv = (const float*)d_in[12];
    const float* kg_w2  = (const float*)d_in[13];
    const float* kg_b2  = (const float*)d_in[14];
    const float* bias   = (const float*)d_in[15];
    const float* ln_w   = (const float*)d_in[16];
    const float* ln_b   = (const float*)d_in[17];
    const float* pw1_w  = (const float*)d_in[18];
    const float* pw1_b  = (const float*)d_in[19];
    const float* pw2_w  = (const float*)d_in[20];
    const float* pw2_b  = (const float*)d_in[21];
    const float* gamma  = (const float*)d_in[22];
    float* outp = (float*)d_out;

    bf16 *pxtok, *pxtok2, *phtok, *pkwtok, *pybf, *pmid, *pw1bf, *pw2bf;
    bf16 *pw1pe, *pw1kg, *pw2pe, *pw2kg;
    float *pxp, *py, *pHw, *pWw;
    cudaGetSymbolAddress((void**)&pxtok,  g_xtok);
    cudaGetSymbolAddress((void**)&pxtok2, g_xtok2);
    cudaGetSymbolAddress((void**)&phtok,  g_htok);
    cudaGetSymbolAddress((void**)&pkwtok, g_kwtok);
    cudaGetSymbolAddress((void**)&pxp, g_xp);
    cudaGetSymbolAddress((void**)&py,  g_y);
    cudaGetSymbolAddress((void**)&pHw, g_Hw);
    cudaGetSymbolAddress((void**)&pWw, g_Ww);
    cudaGetSymbolAddress((void**)&pybf,  g_ybf);
    cudaGetSymbolAddress((void**)&pmid,  g_mid);
    cudaGetSymbolAddress((void**)&pw1bf, g_w1bf);
    cudaGetSymbolAddress((void**)&pw2bf, g_w2bf);
    cudaGetSymbolAddress((void**)&pw1pe, g_w1pe);
    cudaGetSymbolAddress((void**)&pw1kg, g_w1kg);
    cudaGetSymbolAddress((void**)&pw2pe, g_w2pe);
    cudaGetSymbolAddress((void**)&pw2kg, g_w2kg);

    cvt_weights<<<(FDIM * DIM + 255) / 256, 256>>>(pw1_w, pw2_w, pw1bf, pw2bf);
    cvt_convw<<<(MIDC * DIM * 9 + 255) / 256, 256>>>(pe_w1, kg_w1, pe_w2, kg_w2,
                                                     pw1pe, pw1kg, pw2pe, pw2kg);
    nchw2tok<<<dim3(8, 4, BATCH), 256>>>(x, pxtok);

    conv1_tok<<<NTOK / 64, 256>>>(pxtok, pw1pe, pe_bng, pe_bnb, pe_bnm, pe_bnv, phtok);
    conv2_tok<<<dim3(8, NTOK / 128), 256>>>(phtok, pw2pe, pe_b2, pxtok, pxtok2);
    conv1_tok<<<NTOK / 64, 256>>>(pxtok2, pw1kg, kg_bng, kg_bnb, kg_bnm, kg_bnv, phtok);
    conv2_tok<<<dim3(8, NTOK / 128), 256>>>(phtok, pw2kg, kg_b2, nullptr, pkwtok);

    tok2nchw<<<dim3(8, 4, BATCH), 256>>>(pxtok2, pxp);

    reduce_tok<<<dim3(32, BATCH), 512>>>(pkwtok, pHw, pWw);

    circ_kernel<<<(BATCH * DIM) / 4, 256>>>(pxp, pHw, pWw, bias, py);

    ln2_kernel<<<dim3(8, BATCH), 256>>>(py, ln_w, ln_b, pybf);

    gemm1_gelu<<<dim3(FDIM / BN, NTOK / BM), 256>>>(pybf, pw1bf, pw1_b, pmid);
    gemm2_res<<<dim3(DIM / BN, NTOK / BM), 256>>>(pmid, pw2bf, pw2_b, gamma, x, outp);
}

// round 7
// speedup vs baseline: 2.8612x; 1.0500x over previous
#include <cuda_runtime.h>
#include <cuda_bf16.h>
#include <math.h>

#define BATCH 16
#define DIM 512
#define MIDC 32
#define NPIX 1024
#define NTOK 16384
#define FDIM 2048

typedef __nv_bfloat16 bf16;

// ---------------- scratch (static device memory) ----------------
__device__ bf16 g_xtok [NTOK * DIM];
__device__ bf16 g_xtok2[NTOK * DIM];
__device__ bf16 g_htok [NTOK * MIDC];
__device__ bf16 g_kwtok[NTOK * DIM];
__device__ float g_y [BATCH * DIM * NPIX];
__device__ bf16 g_ybf[NTOK * DIM];
__device__ bf16 g_mid[NTOK * FDIM];
__device__ bf16 g_w1bf[FDIM * DIM];
__device__ bf16 g_w2bf[DIM * FDIM];
__device__ bf16 g_w1pe[9 * MIDC * DIM];
__device__ bf16 g_w1kg[9 * MIDC * DIM];
__device__ bf16 g_w2pe[9 * DIM * MIDC];
__device__ bf16 g_w2kg[9 * DIM * MIDC];

// ---------------- cp.async / ldmatrix helpers ----------------
__device__ __forceinline__ void cp16(void* s, const void* g) {
    unsigned sa = (unsigned)__cvta_generic_to_shared(s);
    asm volatile("cp.async.cg.shared.global [%0], [%1], 16;\n" :: "r"(sa), "l"(g));
}
__device__ __forceinline__ void cp16p(void* s, const void* g, bool pred) {
    unsigned sa = (unsigned)__cvta_generic_to_shared(s);
    int sz = pred ? 16 : 0;
    asm volatile("cp.async.cg.shared.global [%0], [%1], 16, %2;\n" :: "r"(sa), "l"(g), "r"(sz));
}
#define CP_COMMIT() asm volatile("cp.async.commit_group;\n")
#define CP_WAIT(n)  asm volatile("cp.async.wait_group %0;\n" :: "n"(n))

__device__ __forceinline__ void ldmx4(unsigned* r, const void* p) {
    unsigned a = (unsigned)__cvta_generic_to_shared(p);
    asm volatile("ldmatrix.sync.aligned.m8n8.x4.shared.b16 {%0,%1,%2,%3}, [%4];\n"
                 : "=r"(r[0]), "=r"(r[1]), "=r"(r[2]), "=r"(r[3]) : "r"(a));
}

// ---------------- merged weight conversion ----------------
__global__ void cvt_all(const float* __restrict__ w1, const float* __restrict__ w2,
                        const float* __restrict__ pw1, const float* __restrict__ kw1,
                        const float* __restrict__ pw2, const float* __restrict__ kw2,
                        bf16* __restrict__ o1, bf16* __restrict__ o2,
                        bf16* __restrict__ o1p, bf16* __restrict__ o1k,
                        bf16* __restrict__ o2p, bf16* __restrict__ o2k)
{
    int i = blockIdx.x * blockDim.x + threadIdx.x;
    if (i < FDIM * DIM) {
        o1[i] = __float2bfloat16(w1[i]);
        o2[i] = __float2bfloat16(w2[i]);
    }
    if (i < MIDC * DIM * 9) {
        int off = i % 9;
        int ic = (i / 9) % DIM, oc = i / (9 * DIM);
        o1p[(off * MIDC + oc) * DIM + ic] = __float2bfloat16(pw1[i]);
        o1k[(off * MIDC + oc) * DIM + ic] = __float2bfloat16(kw1[i]);
        int ic2 = (i / 9) % MIDC, oc2 = i / (9 * MIDC);
        o2p[(off * DIM + oc2) * MIDC + ic2] = __float2bfloat16(pw2[i]);
        o2k[(off * DIM + oc2) * MIDC + ic2] = __float2bfloat16(kw2[i]);
    }
}

// ---------------- NCHW fp32 -> token bf16 transpose ----------------
__global__ __launch_bounds__(256) void nchw2tok(const float* __restrict__ X, bf16* __restrict__ T)
{
    __shared__ bf16 sm[128][136];
    int hw0 = blockIdx.x * 128, c0 = blockIdx.y * 128, b = blockIdx.z;
    int tid = threadIdx.x;
    const float* xp = X + ((size_t)b * DIM + c0) * NPIX + hw0;
#pragma unroll
    for (int i = 0; i < 16; i++) {
        int idx = tid + i * 256;
        int rc = idx >> 5, u = idx & 31;
        float4 v = *(const float4*)&xp[(size_t)rc * NPIX + u * 4];
        union { uint2 q; bf16 h[4]; } pk;
        pk.h[0] = __float2bfloat16(v.x); pk.h[1] = __float2bfloat16(v.y);
        pk.h[2] = __float2bfloat16(v.z); pk.h[3] = __float2bfloat16(v.w);
        *(uint2*)&sm[rc][u * 4] = pk.q;
    }
    __syncthreads();
    bf16* tp = T + ((size_t)(b * NPIX + hw0)) * DIM + c0;
#pragma unroll
    for (int i = 0; i < 8; i++) {
        int idx = tid + i * 256;
        int rt = idx >> 4, uu = idx & 15;
        union { uint4 q; bf16 h[8]; } pk;
#pragma unroll
        for (int j = 0; j < 8; j++) pk.h[j] = sm[uu * 8 + j][rt];
        *(uint4*)&tp[(size_t)rt * DIM + uu * 8] = pk.q;
    }
}

// ---------------- MMA helper ----------------
__device__ __forceinline__ void mma16816(float* d, const unsigned* a, const unsigned* b) {
    asm volatile(
        "mma.sync.aligned.m16n8k16.row.col.f32.bf16.bf16.f32 "
        "{%0,%1,%2,%3}, {%4,%5,%6,%7}, {%8,%9}, {%0,%1,%2,%3};\n"
        : "+f"(d[0]), "+f"(d[1]), "+f"(d[2]), "+f"(d[3])
        : "r"(a[0]), "r"(a[1]), "r"(a[2]), "r"(a[3]), "r"(b[0]), "r"(b[1]));
}

// ---------------- conv1: 512-thread dual-warpgroup K-split -----------------
// M tile 64, N=32. 36 pairs of 64-k tiles (128 k per iteration, 1 barrier each).
#define C1S 72
#define C1_AS_BYTES (6 * 64 * C1S * 2)
#define C1_BS_BYTES (6 * 32 * C1S * 2)
#define C1_PB_BYTES (8 * 16 * 16 * 4)
#define C1_SMEM (C1_AS_BYTES + C1_BS_BYTES + C1_PB_BYTES + 256)
__global__ __launch_bounds__(512) void conv1_tok(
    const bf16* __restrict__ X, const bf16* __restrict__ W,
    const float* __restrict__ bng, const float* __restrict__ bnb,
    const float* __restrict__ bnm, const float* __restrict__ bnv,
    bf16* __restrict__ O)
{
    extern __shared__ __align__(16) char dsm[];
    bf16 (*As)[64][C1S] = (bf16(*)[64][C1S])dsm;
    bf16 (*Bs)[32][C1S] = (bf16(*)[32][C1S])(dsm + C1_AS_BYTES);
    float (*pbuf)[16][16] = (float(*)[16][16])(dsm + C1_AS_BYTES + C1_BS_BYTES);
    float* sS = (float*)(dsm + C1_AS_BYTES + C1_BS_BYTES + C1_PB_BYTES);
    float* sT = sS + 32;

    int m0 = blockIdx.x * 64;
    int tid = threadIdx.x;
    if (tid < 32) {
        float inv = rsqrtf(bnv[tid] + 1e-5f);
        float s = bng[tid] * inv;
        sS[tid] = s;
        sT[tid] = bnb[tid] - bnm[tid] * s;
    }
    int ar = tid >> 3, aq = (tid & 7) * 16;   // A: 64 rows x 8 chunks of 16 elems
    int asub = aq >> 6, acol = aq & 63;
    int t = m0 + ar;
    int th = (t >> 5) & 31, tw = t & 31;
    int br = (tid & 255) >> 3, bq = (tid & 7) * 16;
    int bsub = bq >> 6, bcol = bq & 63;
    int wid = tid >> 5, lane = tid & 31;
    int wg = wid >> 3, wl = wid & 7;
    int wm = (wl & 3) * 16, wn = (wl >> 2) * 16;
    int g = lane >> 2, tg = lane & 3;
    int lrow = (lane & 7) + ((lane >> 3) & 1) * 8;
    int lcol = ((lane >> 4) & 1) * 8;

    float acc[2][4];
#pragma unroll
    for (int i = 0; i < 2; i++)
#pragma unroll
        for (int j = 0; j < 4; j++) acc[i][j] = 0.f;

    auto load_pair = [&](int p, int ds) {
        int off = p >> 2, k0 = (p & 3) * 128;
        int dy = off / 3 - 1, dx = off % 3 - 1;
        bool valid = ((unsigned)(th + dy) < 32u) && ((unsigned)(tw + dx) < 32u);
        const bf16* srcA = X + ((long)(t + dy * 32 + dx)) * DIM + k0 + aq;
        cp16p(&As[ds * 2 + asub][ar][acol],     srcA,     valid);
        cp16p(&As[ds * 2 + asub][ar][acol + 8], srcA + 8, valid);
        if (tid < 256) {
            const bf16* srcB = W + (size_t)(off * MIDC + br) * DIM + k0 + bq;
            cp16(&Bs[ds * 2 + bsub][br][bcol],     srcB);
            cp16(&Bs[ds * 2 + bsub][br][bcol + 8], srcB + 8);
        }
    };

    load_pair(0, 0);
    CP_COMMIT();
    load_pair(1, 1);
    CP_COMMIT();
    for (int p = 0; p < 36; p++) {
        int ds = p % 3;
        if (p + 1 < 36) { CP_WAIT(1); } else { CP_WAIT(0); }
        __syncthreads();
        if (p + 2 < 36) {
            load_pair(p + 2, (p + 2) % 3);
            CP_COMMIT();
        }
        int buf = ds * 2 + wg;
#pragma unroll
        for (int kc = 0; kc < 4; kc++) {
            int kb = kc * 16;
            unsigned a[4], bb[4];
            ldmx4(a,  &As[buf][wm + lrow][kb + lcol]);
            ldmx4(bb, &Bs[buf][wn + lrow][kb + lcol]);
            unsigned b0[2] = { bb[0], bb[2] };
            unsigned b1[2] = { bb[1], bb[3] };
            mma16816(acc[0], a, b0);
            mma16816(acc[1], a, b1);
        }
    }
    // K-split reduction: WG1 dumps partials, WG0 adds + BN + ReLU + store
    if (wg == 1) {
#pragma unroll
        for (int ni = 0; ni < 2; ni++)
#pragma unroll
            for (int rr = 0; rr < 2; rr++)
#pragma unroll
                for (int j = 0; j < 2; j++)
                    pbuf[wl][g + rr * 8][ni * 8 + tg * 2 + j] = acc[ni][rr * 2 + j];
    }
    __syncthreads();
    if (wg == 0) {
#pragma unroll
        for (int ni = 0; ni < 2; ni++)
#pragma unroll
            for (int rr = 0; rr < 2; rr++) {
                int col = wn + ni * 8 + tg * 2;
                int row = wm + g + rr * 8;
                float v0 = acc[ni][rr * 2 + 0] + pbuf[wl][g + rr * 8][ni * 8 + tg * 2 + 0];
                float v1 = acc[ni][rr * 2 + 1] + pbuf[wl][g + rr * 8][ni * 8 + tg * 2 + 1];
                v0 = fmaxf(v0 * sS[col]     + sT[col],     0.f);
                v1 = fmaxf(v1 * sS[col + 1] + sT[col + 1], 0.f);
                __nv_bfloat162 pk;
                pk.x = __float2bfloat16(v0);
                pk.y = __float2bfloat16(v1);
                *(__nv_bfloat162*)&O[(size_t)(m0 + row) * MIDC + col] = pk;
            }
    }
}

// ---------------- conv2 implicit GEMM (2-stage cp.async + ldmatrix) ---------
__global__ __launch_bounds__(256) void conv2_tok(
    const bf16* __restrict__ Hx, const bf16* __restrict__ W,
    const float* __restrict__ b2, const bf16* __restrict__ res,
    bf16* __restrict__ O)
{
    __shared__ __align__(16) bf16 As[2][128][40];
    __shared__ __align__(16) bf16 Bs[2][64][40];
    int n0 = blockIdx.x * 64, m0 = blockIdx.y * 128;
    int tid = threadIdx.x;
    int ar = tid >> 1, aq = (tid & 1) * 16;
    int t = m0 + ar;
    int th = (t >> 5) & 31, tw = t & 31;
    int br = tid >> 2, bq = (tid & 3) * 8;
    int wid = tid >> 5, lane = tid & 31;
    int wm = (wid & 3) * 32, wn = (wid >> 2) * 32;
    int g = lane >> 2, tg = lane & 3;
    int lrow = (lane & 7) + ((lane >> 3) & 1) * 8;
    int lcol = ((lane >> 4) & 1) * 8;

    float acc[2][4][4];
#pragma unroll
    for (int i = 0; i < 2; i++)
#pragma unroll
        for (int j = 0; j < 4; j++)
#pragma unroll
            for (int k = 0; k < 4; k++) acc[i][j][k] = 0.f;

    auto load_tile = [&](int off, int buf) {
        int dy = off / 3 - 1, dx = off % 3 - 1;
        bool valid = ((unsigned)(th + dy) < 32u) && ((unsigned)(tw + dx) < 32u);
        const bf16* srcA = Hx + ((long)(t + dy * 32 + dx)) * MIDC + aq;
        cp16p(&As[buf][ar][aq], srcA, valid);
        cp16p(&As[buf][ar][aq + 8], srcA + 8, valid);
        cp16(&Bs[buf][br][bq], &W[(size_t)(off * DIM + n0 + br) * MIDC + bq]);
    };

    load_tile(0, 0);
    CP_COMMIT();
    for (int off = 0; off < 9; off++) {
        int buf = off & 1;
        if (off < 8) {
            load_tile(off + 1, buf ^ 1);
            CP_COMMIT();
            CP_WAIT(1);
        } else {
            CP_WAIT(0);
        }
        __syncthreads();
#pragma unroll
        for (int kc = 0; kc < 2; kc++) {
            int kb = kc * 16;
            unsigned a[2][4], bb[2][4];
#pragma unroll
            for (int mi = 0; mi < 2; mi++)
                ldmx4(a[mi], &As[buf][wm + mi * 16 + lrow][kb + lcol]);
#pragma unroll
            for (int nh = 0; nh < 2; nh++)
                ldmx4(bb[nh], &Bs[buf][wn + nh * 16 + lrow][kb + lcol]);
#pragma unroll
            for (int mi = 0; mi < 2; mi++)
#pragma unroll
                for (int ni = 0; ni < 4; ni++) {
                    unsigned bfr[2] = { bb[ni >> 1][ni & 1], bb[ni >> 1][(ni & 1) + 2] };
                    mma16816(acc[mi][ni], a[mi], bfr);
                }
        }
        __syncthreads();
    }
    float bv0[4], bv1[4];
#pragma unroll
    for (int ni = 0; ni < 4; ni++) {
        int col = n0 + wn + ni * 8 + tg * 2;
        bv0[ni] = b2[col];
        bv1[ni] = b2[col + 1];
    }
#pragma unroll
    for (int mi = 0; mi < 2; mi++)
#pragma unroll
        for (int ni = 0; ni < 4; ni++)
#pragma unroll
            for (int rr = 0; rr < 2; rr++) {
                int row = m0 + wm + mi * 16 + g + rr * 8;
                size_t ad = (size_t)row * DIM + n0 + wn + ni * 8 + tg * 2;
                float v0 = acc[mi][ni][rr * 2 + 0] + bv0[ni];
                float v1 = acc[mi][ni][rr * 2 + 1] + bv1[ni];
                if (res) {
                    __nv_bfloat162 rv = *(const __nv_bfloat162*)&res[ad];
                    v0 += __bfloat162float(rv.x);
                    v1 += __bfloat162float(rv.y);
                }
                __nv_bfloat162 p;
                p.x = __float2bfloat16(v0);
                p.y = __float2bfloat16(v1);
                *(__nv_bfloat162*)&O[ad] = p;
            }
}

// ---------------- circ: reads tokens, computes means internally -------------
__global__ __launch_bounds__(256) void circ_tok(
    const bf16* __restrict__ Xt, const bf16* __restrict__ KWt,
    const float* __restrict__ bias, float* __restrict__ y)
{
    __shared__ float xs[4][32][36];
    __shared__ float ks[4][32][36];
    __shared__ float kv[4][32];
    int p0 = blockIdx.x * 4;
    int b = p0 >> 9;
    int c0 = p0 & 511;
    int tid = threadIdx.x;
    int lp = tid >> 6, lt = tid & 63;
    int c = c0 + lp;

#pragma unroll
    for (int i = 0; i < 4; i++) {
        int tok = tid + i * 256;
        int hh = tok >> 5, ww = tok & 31;
        size_t base = (size_t)(b * NPIX + tok) * DIM + c0;
        uint2 xv = *(const uint2*)&Xt[base];
        uint2 kw = *(const uint2*)&KWt[base];
        const __nv_bfloat162* xh = (const __nv_bfloat162*)&xv;
        const __nv_bfloat162* kh = (const __nv_bfloat162*)&kw;
        xs[0][hh][ww] = __bfloat162float(xh[0].x);
        xs[1][hh][ww] = __bfloat162float(xh[0].y);
        xs[2][hh][ww] = __bfloat162float(xh[1].x);
        xs[3][hh][ww] = __bfloat162float(xh[1].y);
        ks[0][hh][ww] = __bfloat162float(kh[0].x);
        ks[1][hh][ww] = __bfloat162float(kh[0].y);
        ks[2][hh][ww] = __bfloat162float(kh[1].x);
        ks[3][hh][ww] = __bfloat162float(kh[1].y);
    }
    __syncthreads();
    if (lt < 32) {
        float s = 0.f;
        if (c < 256) {
#pragma unroll
            for (int ww = 0; ww < 32; ww++) s += ks[lp][lt][ww];
        } else {
#pragma unroll
            for (int hh = 0; hh < 32; hh++) s += ks[lp][hh][lt];
        }
        kv[lp][lt] = s * (1.f / 32.f);
    }
    __syncthreads();

    int t_r = (lt >> 3) * 4;
    int t_c = (lt & 7) * 4;
    float acc[4][4];
#pragma unroll
    for (int r = 0; r < 4; r++)
#pragma unroll
        for (int cc2 = 0; cc2 < 4; cc2++) acc[r][cc2] = 0.f;
    float bv = bias[c];

    if (c < 256) {
        float kr[32];
#pragma unroll
        for (int u = 0; u < 32; u++) kr[u] = kv[lp][(u - t_r) & 31];
#pragma unroll
        for (int j = 0; j < 32; j++) {
            float4 xv = *(const float4*)&xs[lp][j][t_c];
#pragma unroll
            for (int ri = 0; ri < 4; ri++) {
                float kk = kr[(j - ri) & 31];
                acc[ri][0] += kk * xv.x;
                acc[ri][1] += kk * xv.y;
                acc[ri][2] += kk * xv.z;
                acc[ri][3] += kk * xv.w;
            }
        }
    } else {
        float kr[32];
#pragma unroll
        for (int u = 0; u < 32; u++) kr[u] = kv[lp][(u - t_c) & 31];
#pragma unroll
        for (int j = 0; j < 32; j++) {
            float xv[4];
#pragma unroll
            for (int ri = 0; ri < 4; ri++) xv[ri] = xs[lp][t_r + ri][j];
#pragma unroll
            for (int ci = 0; ci < 4; ci++) {
                float kk = kr[(j - ci) & 31];
#pragma unroll
                for (int ri = 0; ri < 4; ri++) acc[ri][ci] += kk * xv[ri];
            }
        }
    }
    float* yp = y + (size_t)(p0 + lp) * NPIX;
#pragma unroll
    for (int ri = 0; ri < 4; ri++) {
        float4 o;
        o.x = acc[ri][0] + bv; o.y = acc[ri][1] + bv;
        o.z = acc[ri][2] + bv; o.w = acc[ri][3] + bv;
        *(float4*)&yp[(t_r + ri) * 32 + t_c] = o;
    }
}

// ---------------- LayerNorm: 64 tokens/block, quarter-channel threads -------
__global__ __launch_bounds__(256) void ln2_kernel(
    const float* __restrict__ Y, const float* __restrict__ lnw,
    const float* __restrict__ lnb, bf16* __restrict__ O)
{
    __shared__ float red[256], red2[256];
    __shared__ float mus[64], rss[64];
    int chunk = blockIdx.x, b = blockIdx.y;
    int hw0 = chunk * 64;
    int tid = threadIdx.x;
    int j = tid & 63, q = tid >> 6;
    const float* yb = Y + (size_t)b * DIM * NPIX + hw0 + j;
    float s = 0.f, s2 = 0.f;
    for (int c = q * 128; c < q * 128 + 128; c++) {
        float v = yb[(size_t)c * NPIX];
        s += v; s2 += v * v;
    }
    red[tid] = s; red2[tid] = s2;
    __syncthreads();
    if (tid < 64) {
        float S = red[tid] + red[tid + 64] + red[tid + 128] + red[tid + 192];
        float S2 = red2[tid] + red2[tid + 64] + red2[tid + 128] + red2[tid + 192];
        float mu = S * (1.f / 512.f);
        float var = S2 * (1.f / 512.f) - mu * mu;
        mus[tid] = mu;
        rss[tid] = rsqrtf(var + 1e-6f);
    }
    __syncthreads();
    float mu = mus[j], rstd = rss[j];
    size_t t0 = (size_t)b * NPIX + hw0;
    for (int c8 = q * 128; c8 < q * 128 + 128; c8 += 8) {
        union { uint4 u; bf16 h[8]; } pk;
#pragma unroll
        for (int i = 0; i < 8; i++) {
            int c = c8 + i;
            float v = yb[(size_t)c * NPIX];
            pk.h[i] = __float2bfloat16((v - mu) * rstd * __ldg(&lnw[c]) + __ldg(&lnb[c]));
        }
        *(uint4*)&O[(t0 + j) * DIM + c8] = pk.u;
    }
}

__device__ __forceinline__ float gelu_exact(float x) {
    return 0.5f * x * (1.f + erff(x * 0.70710678118654752f));
}

#define BM 128
#define BN 128
#define SSTR 40

// GEMM1: C = gelu(A * W1^T + b)  (3-stage)
__global__ __launch_bounds__(256) void gemm1_gelu(
    const bf16* __restrict__ A, const bf16* __restrict__ Bw,
    const float* __restrict__ bias, bf16* __restrict__ C)
{
    const int K = DIM, KT = K / 32;
    __shared__ __align__(16) bf16 As[3][BM][SSTR];
    __shared__ __align__(16) bf16 Bs[3][BN][SSTR];
    int m0 = blockIdx.y * BM, n0 = blockIdx.x * BN;
    int tid = threadIdx.x;
    int wid = tid >> 5, lane = tid & 31;
    int wm = (wid & 1) * 64, wn = (wid >> 1) * 32;
    int g = lane >> 2, tg = lane & 3;
    int lrow = (lane & 7) + ((lane >> 3) & 1) * 8;
    int lcol = ((lane >> 4) & 1) * 8;
    float acc[4][4][4];
#pragma unroll
    for (int i = 0; i < 4; i++)
#pragma unroll
        for (int j = 0; j < 4; j++)
#pragma unroll
            for (int k = 0; k < 4; k++) acc[i][j][k] = 0.f;

    int lr = tid >> 1, lc = (tid & 1) * 16;
    const bf16* apb = &A[(size_t)(m0 + lr) * K + lc];
    const bf16* bpb = &Bw[(size_t)(n0 + lr) * K + lc];

    auto load_tile = [&](int kt, int buf) {
        cp16(&As[buf][lr][lc],     apb + kt * 32);
        cp16(&As[buf][lr][lc + 8], apb + kt * 32 + 8);
        cp16(&Bs[buf][lr][lc],     bpb + kt * 32);
        cp16(&Bs[buf][lr][lc + 8], bpb + kt * 32 + 8);
    };

    load_tile(0, 0);
    CP_COMMIT();
    load_tile(1, 1);
    CP_COMMIT();
    for (int kt = 0; kt < KT; kt++) {
        int buf = kt % 3;
        if (kt + 1 < KT) { CP_WAIT(1); } else { CP_WAIT(0); }
        __syncthreads();
        if (kt + 2 < KT) {
            load_tile(kt + 2, (kt + 2) % 3);
            CP_COMMIT();
        }
#pragma unroll
        for (int ks = 0; ks < 2; ks++) {
            int kb = ks * 16;
            unsigned af[4][4], bb[2][4];
#pragma unroll
            for (int mi = 0; mi < 4; mi++)
                ldmx4(af[mi], &As[buf][wm + mi * 16 + lrow][kb + lcol]);
#pragma unroll
            for (int nh = 0; nh < 2; nh++)
                ldmx4(bb[nh], &Bs[buf][wn + nh * 16 + lrow][kb + lcol]);
#pragma unroll
            for (int mi = 0; mi < 4; mi++)
#pragma unroll
                for (int ni = 0; ni < 4; ni++) {
                    unsigned bfr[2] = { bb[ni >> 1][ni & 1], bb[ni >> 1][(ni & 1) + 2] };
                    mma16816(acc[mi][ni], af[mi], bfr);
                }
        }
    }
#pragma unroll
    for (int mi = 0; mi < 4; mi++)
#pragma unroll
        for (int ni = 0; ni < 4; ni++) {
            int col = n0 + wn + ni * 8 + tg * 2;
            float b0 = bias[col], b1 = bias[col + 1];
            int row0 = m0 + wm + mi * 16 + g;
#pragma unroll
            for (int rr = 0; rr < 2; rr++) {
                int r = row0 + rr * 8;
                float v0 = gelu_exact(acc[mi][ni][rr * 2 + 0] + b0);
                float v1 = gelu_exact(acc[mi][ni][rr * 2 + 1] + b1);
                __nv_bfloat162 p;
                p.x = __float2bfloat16(v0);
                p.y = __float2bfloat16(v1);
                *(__nv_bfloat162*)&C[(size_t)r * FDIM + col] = p;
            }
        }
}

// GEMM2: out = x_in + gamma*(A*W2^T + b), 3-stage + coalesced NCHW epilogue
__global__ __launch_bounds__(256) void gemm2_res(
    const bf16* __restrict__ A, const bf16* __restrict__ Bw,
    const float* __restrict__ bias2, const float* __restrict__ gamma,
    const float* __restrict__ xin, float* __restrict__ out)
{
    const int K = FDIM, KT = K / 32;
    __shared__ __align__(16) char sm_raw[3 * BM * SSTR * 2 + 3 * BN * SSTR * 2];
    bf16 (*As)[BM][SSTR] = (bf16(*)[BM][SSTR])sm_raw;
    bf16 (*Bs)[BN][SSTR] = (bf16(*)[BN][SSTR])(sm_raw + 3 * BM * SSTR * 2);
    int m0 = blockIdx.y * BM, n0 = blockIdx.x * BN;
    int tid = threadIdx.x;
    int wid = tid >> 5, lane = tid & 31;
    int wm = (wid & 1) * 64, wn = (wid >> 1) * 32;
    int g = lane >> 2, tg = lane & 3;
    int lrow = (lane & 7) + ((lane >> 3) & 1) * 8;
    int lcol = ((lane >> 4) & 1) * 8;
    float acc[4][4][4];
#pragma unroll
    for (int i = 0; i < 4; i++)
#pragma unroll
        for (int j = 0; j < 4; j++)
#pragma unroll
            for (int k = 0; k < 4; k++) acc[i][j][k] = 0.f;

    int lr = tid >> 1, lc = (tid & 1) * 16;
    const bf16* apb = &A[(size_t)(m0 + lr) * K + lc];
    const bf16* bpb = &Bw[(size_t)(n0 + lr) * K + lc];

    auto load_tile = [&](int kt, int buf) {
        cp16(&As[buf][lr][lc],     apb + kt * 32);
        cp16(&As[buf][lr][lc + 8], apb + kt * 32 + 8);
        cp16(&Bs[buf][lr][lc],     bpb + kt * 32);
        cp16(&Bs[buf][lr][lc + 8], bpb + kt * 32 + 8);
    };

    load_tile(0, 0);
    CP_COMMIT();
    load_tile(1, 1);
    CP_COMMIT();
    for (int kt = 0; kt < KT; kt++) {
        int buf = kt % 3;
        if (kt + 1 < KT) { CP_WAIT(1); } else { CP_WAIT(0); }
        __syncthreads();
        if (kt + 2 < KT) {
            load_tile(kt + 2, (kt + 2) % 3);
            CP_COMMIT();
        }
#pragma unroll
        for (int ks = 0; ks < 2; ks++) {
            int kb = ks * 16;
            unsigned af[4][4], bb[2][4];
#pragma unroll
            for (int mi = 0; mi < 4; mi++)
                ldmx4(af[mi], &As[buf][wm + mi * 16 + lrow][kb + lcol]);
#pragma unroll
            for (int nh = 0; nh < 2; nh++)
                ldmx4(bb[nh], &Bs[buf][wn + nh * 16 + lrow][kb + lcol]);
#pragma unroll
            for (int mi = 0; mi < 4; mi++)
#pragma unroll
                for (int ni = 0; ni < 4; ni++) {
                    unsigned bfr[2] = { bb[ni >> 1][ni & 1], bb[ni >> 1][(ni & 1) + 2] };
                    mma16816(acc[mi][ni], af[mi], bfr);
                }
        }
    }
    __syncthreads();
    float (*sbuf)[33] = (float(*)[33])sm_raw;
    int cc = tid >> 3, seg = tid & 7;
#pragma unroll
    for (int nc = 0; nc < 4; nc++) {
        if ((wid >> 1) == nc) {
#pragma unroll
            for (int mi = 0; mi < 4; mi++)
#pragma unroll
                for (int ni = 0; ni < 4; ni++)
#pragma unroll
                    for (int rr = 0; rr < 2; rr++)
#pragma unroll
                        for (int j = 0; j < 2; j++)
                            sbuf[wm + mi * 16 + g + rr * 8][ni * 8 + tg * 2 + j] =
                                acc[mi][ni][rr * 2 + j];
        }
        __syncthreads();
        int col = n0 + nc * 32 + cc;
        float gb = gamma[col], bb2 = bias2[col];
        size_t colbase = ((size_t)(m0 >> 10) * DIM + col) * NPIX + (m0 & 1023);
#pragma unroll
        for (int q = 0; q < 4; q++) {
            int r = q * 32 + seg * 4;
            float4 xv = *(const float4*)&xin[colbase + r];
            float4 o;
            o.x = xv.x + gb * (sbuf[r + 0][cc] + bb2);
            o.y = xv.y + gb * (sbuf[r + 1][cc] + bb2);
            o.z = xv.z + gb * (sbuf[r + 2][cc] + bb2);
            o.w = xv.w + gb * (sbuf[r + 3][cc] + bb2);
            *(float4*)&out[colbase + r] = o;
        }
        __syncthreads();
    }
}

// ---------------- host launcher ----------------
extern "C" void kernel_launch(void* const* d_in, const int* in_sizes, int n_in,
                              void* d_out, int out_size)
{
    const float* x      = (const float*)d_in[0];
    const float* pe_w1  = (const float*)d_in[1];
    const float* pe_bng = (const float*)d_in[2];
    const float* pe_bnb = (const float*)d_in[3];
    const float* pe_bnm = (const float*)d_in[4];
    const float* pe_bnv = (const float*)d_in[5];
    const float* pe_w2  = (const float*)d_in[6];
    const float* pe_b2  = (const float*)d_in[7];
    const float* kg_w1  = (const float*)d_in[8];
    const float* kg_bng = (const float*)d_in[9];
    const float* kg_bnb = (const float*)d_in[10];
    const float* kg_bnm = (const float*)d_in[11];
    const float* kg_bnv = (const float*)d_in[12];
    const float* kg_w2  = (const float*)d_in[13];
    const float* kg_b2  = (const float*)d_in[14];
    const float* bias   = (const float*)d_in[15];
    const float* ln_w   = (const float*)d_in[16];
    const float* ln_b   = (const float*)d_in[17];
    const float* pw1_w  = (const float*)d_in[18];
    const float* pw1_b  = (const float*)d_in[19];
    const float* pw2_w  = (const float*)d_in[20];
    const float* pw2_b  = (const float*)d_in[21];
    const float* gamma  = (const float*)d_in[22];
    float* outp = (float*)d_out;

    bf16 *pxtok, *pxtok2, *phtok, *pkwtok, *pybf, *pmid, *pw1bf, *pw2bf;
    bf16 *pw1pe, *pw1kg, *pw2pe, *pw2kg;
    float *py;
    cudaGetSymbolAddress((void**)&pxtok,  g_xtok);
    cudaGetSymbolAddress((void**)&pxtok2, g_xtok2);
    cudaGetSymbolAddress((void**)&phtok,  g_htok);
    cudaGetSymbolAddress((void**)&pkwtok, g_kwtok);
    cudaGetSymbolAddress((void**)&py,  g_y);
    cudaGetSymbolAddress((void**)&pybf,  g_ybf);
    cudaGetSymbolAddress((void**)&pmid,  g_mid);
    cudaGetSymbolAddress((void**)&pw1bf, g_w1bf);
    cudaGetSymbolAddress((void**)&pw2bf, g_w2bf);
    cudaGetSymbolAddress((void**)&pw1pe, g_w1pe);
    cudaGetSymbolAddress((void**)&pw1kg, g_w1kg);
    cudaGetSymbolAddress((void**)&pw2pe, g_w2pe);
    cudaGetSymbolAddress((void**)&pw2kg, g_w2kg);

    cudaFuncSetAttribute(conv1_tok, cudaFuncAttributeMaxDynamicSharedMemorySize, C1_SMEM);

    cvt_all<<<(FDIM * DIM + 255) / 256, 256>>>(pw1_w, pw2_w, pe_w1, kg_w1, pe_w2, kg_w2,
                                               pw1bf, pw2bf, pw1pe, pw1kg, pw2pe, pw2kg);
    nchw2tok<<<dim3(8, 4, BATCH), 256>>>(x, pxtok);

    conv1_tok<<<NTOK / 64, 512, C1_SMEM>>>(pxtok, pw1pe, pe_bng, pe_bnb, pe_bnm, pe_bnv, phtok);
    conv2_tok<<<dim3(8, NTOK / 128), 256>>>(phtok, pw2pe, pe_b2, pxtok, pxtok2);
    conv1_tok<<<NTOK / 64, 512, C1_SMEM>>>(pxtok2, pw1kg, kg_bng, kg_bnb, kg_bnm, kg_bnv, phtok);
    conv2_tok<<<dim3(8, NTOK / 128), 256>>>(phtok, pw2kg, kg_b2, nullptr, pkwtok);

    circ_tok<<<(BATCH * DIM) / 4, 256>>>(pxtok2, pkwtok, bias, py);

    ln2_kernel<<<dim3(16, BATCH), 256>>>(py, ln_w, ln_b, pybf);

    gemm1_gelu<<<dim3(FDIM / BN, NTOK / BM), 256>>>(pybf, pw1bf, pw1_b, pmid);
    gemm2_res<<<dim3(DIM / BN, NTOK / BM), 256>>>(pmid, pw2bf, pw2_b, gamma, x, outp);
}